// round 11
// baseline (speedup 1.0000x reference)
#include <cuda_runtime.h>
#include <cuda_bf16.h>
#include <cstdint>

#define BATCH 4
#define CH    256
#define SP    4096
#define DH    256

__device__ __align__(16) __nv_bfloat16 g_xh[BATCH * CH * SP];
__device__ __align__(16) __nv_bfloat16 g_xl[BATCH * CH * SP];
__device__ __align__(16) __nv_bfloat16 g_wh[4 * 65536];
__device__ __align__(16) __nv_bfloat16 g_wl[4 * 65536];
__device__ __align__(16) __nv_bfloat16 g_qh[BATCH * CH * SP];
__device__ __align__(16) __nv_bfloat16 g_ql[BATCH * CH * SP];
__device__ __align__(16) __nv_bfloat16 g_kh[BATCH * CH * SP];
__device__ __align__(16) __nv_bfloat16 g_kl[BATCH * CH * SP];
__device__ __align__(16) __nv_bfloat16 g_vh[BATCH * CH * SP];
__device__ __align__(16) __nv_bfloat16 g_vl[BATCH * CH * SP];
__device__ __align__(16) __nv_bfloat16 g_ah[BATCH * CH * SP];
__device__ __align__(16) __nv_bfloat16 g_al[BATCH * CH * SP];

// ---------------- helpers ----------------
__device__ __forceinline__ uint32_t pk(float x0, float x1) {
    uint32_t r;
    asm("cvt.rn.bf16x2.f32 %0, %1, %2;" : "=r"(r) : "f"(x1), "f"(x0));
    return r;
}
__device__ __forceinline__ void split2(float x0, float x1, uint32_t& hi, uint32_t& lo) {
    float h0 = __bfloat162float(__float2bfloat16(x0));
    float h1 = __bfloat162float(__float2bfloat16(x1));
    hi = pk(x0, x1);
    lo = pk(x0 - h0, x1 - h1);
}
__device__ __forceinline__ void ldsm4(uint32_t* r, uint32_t a) {
    asm volatile("ldmatrix.sync.aligned.m8n8.x4.shared.b16 {%0,%1,%2,%3}, [%4];"
                 : "=r"(r[0]), "=r"(r[1]), "=r"(r[2]), "=r"(r[3]) : "r"(a));
}
__device__ __forceinline__ void ldsm4t(uint32_t* r, uint32_t a) {
    asm volatile("ldmatrix.sync.aligned.m8n8.x4.trans.shared.b16 {%0,%1,%2,%3}, [%4];"
                 : "=r"(r[0]), "=r"(r[1]), "=r"(r[2]), "=r"(r[3]) : "r"(a));
}
__device__ __forceinline__ void mma16816(float* d, const uint32_t* a, uint32_t b0, uint32_t b1) {
    asm volatile("mma.sync.aligned.m16n8k16.row.col.f32.bf16.bf16.f32 "
                 "{%0,%1,%2,%3}, {%4,%5,%6,%7}, {%8,%9}, {%0,%1,%2,%3};"
                 : "+f"(d[0]), "+f"(d[1]), "+f"(d[2]), "+f"(d[3])
                 : "r"(a[0]), "r"(a[1]), "r"(a[2]), "r"(a[3]), "r"(b0), "r"(b1));
}
__device__ __forceinline__ uint32_t sm_u32(const void* p) {
    return (uint32_t)__cvta_generic_to_shared(p);
}
__device__ __forceinline__ void cpa16(uint32_t dst, const void* src) {
    asm volatile("cp.async.cg.shared.global [%0], [%1], 16;" :: "r"(dst), "l"(src));
}
__device__ __forceinline__ void cpa_commit() { asm volatile("cp.async.commit_group;"); }
__device__ __forceinline__ void cpa_wait_all() { asm volatile("cp.async.wait_group 0;"); }

// ---------------------------------------------------------------------------
// Split kernels: fp32 -> bf16 hi/lo
// ---------------------------------------------------------------------------
__global__ __launch_bounds__(256) void splitx_kernel(const float* __restrict__ x)
{
    size_t i = ((size_t)blockIdx.x * 256 + threadIdx.x) * 4;
    float4 v = *(const float4*)(x + i);
    uint32_t h0, l0, h1, l1;
    split2(v.x, v.y, h0, l0);
    split2(v.z, v.w, h1, l1);
    uint2 hw, lw;
    hw.x = h0; hw.y = h1; lw.x = l0; lw.y = l1;
    *(uint2*)&g_xh[i] = hw;
    *(uint2*)&g_xl[i] = lw;
}

__global__ __launch_bounds__(256) void splitw_kernel(
    const float* __restrict__ Wq, const float* __restrict__ Wk,
    const float* __restrict__ Wv, const float* __restrict__ Wu)
{
    size_t i = ((size_t)blockIdx.x * 256 + threadIdx.x) * 4;
    int which = (int)(i >> 16);
    const float* W = (which == 0) ? Wq : (which == 1) ? Wk : (which == 2) ? Wv : Wu;
    float4 v = *(const float4*)(W + (i & 65535));
    uint32_t h0, l0, h1, l1;
    split2(v.x, v.y, h0, l0);
    split2(v.z, v.w, h1, l1);
    uint2 hw, lw;
    hw.x = h0; hw.y = h1; lw.x = l0; lw.y = l1;
    *(uint2*)&g_wh[i] = hw;
    *(uint2*)&g_wl[i] = lw;
}

// ---------------------------------------------------------------------------
// Conv GEMM on tensor cores (bf16 hi/lo, 3-term). CTA: 128(out-ch) x 128(sp).
// ---------------------------------------------------------------------------
#define STG 21504
#define WL_OFF 6144
#define XH_OFF 12288
#define XL_OFF 16640

__device__ __forceinline__ void conv_issue(
    uint32_t sb, int tid, int kc,
    const __nv_bfloat16* gwh, const __nv_bfloat16* gwl,
    const __nv_bfloat16* xh, const __nv_bfloat16* xl,
    int m0, int s0)
{
    int mm = tid & 127, g = tid >> 7;
    const __nv_bfloat16* swh = gwh + (size_t)(m0 + mm) * 256 + kc * 16 + g * 8;
    const __nv_bfloat16* swl = gwl + (size_t)(m0 + mm) * 256 + kc * 16 + g * 8;
    cpa16(sb + mm * 48 + g * 16, swh);
    cpa16(sb + WL_OFF + mm * 48 + g * 16, swl);
    int kk = tid >> 4, sg = (tid & 15) * 8;
    const __nv_bfloat16* sxh = xh + (size_t)(kc * 16 + kk) * SP + s0 + sg;
    const __nv_bfloat16* sxl = xl + (size_t)(kc * 16 + kk) * SP + s0 + sg;
    cpa16(sb + XH_OFF + kk * 272 + sg * 2, sxh);
    cpa16(sb + XL_OFF + kk * 272 + sg * 2, sxl);
}

__device__ __forceinline__ void conv_gemm_body(
    float acc[16][4], uint32_t smb, int tid,
    const __nv_bfloat16* gwh, const __nv_bfloat16* gwl,
    const __nv_bfloat16* xh, const __nv_bfloat16* xl,
    int m0, int s0)
{
    int w = tid >> 5, lane = tid & 31;
    int rsel = lane & 15, csel = lane >> 4;

    conv_issue(smb, tid, 0, gwh, gwl, xh, xl, m0, s0);
    cpa_commit();

    for (int kc = 0; kc < 16; kc++) {
        cpa_wait_all();
        __syncthreads();
        if (kc < 15) {
            conv_issue(smb + ((kc + 1) & 1) * STG, tid, kc + 1, gwh, gwl, xh, xl, m0, s0);
            cpa_commit();
        }
        uint32_t base = smb + (kc & 1) * STG;
        uint32_t aW  = base + (16 * w + rsel) * 48 + csel * 16;
        uint32_t aWl = aW + WL_OFF;
        uint32_t aX  = base + XH_OFF + rsel * 272 + csel * 16;
        uint32_t aXl = aX + (XL_OFF - XH_OFF);

        uint32_t awh[4], awl[4];
        ldsm4(awh, aW);
        ldsm4(awl, aWl);
#pragma unroll
        for (int nt = 0; nt < 8; nt++) {
            uint32_t bxh[4], bxl[4];
            ldsm4t(bxh, aX + nt * 32);
            ldsm4t(bxl, aXl + nt * 32);
            float* oA = acc[2 * nt];
            float* oB = acc[2 * nt + 1];
            mma16816(oA, awh, bxh[0], bxh[1]);
            mma16816(oA, awh, bxl[0], bxl[1]);
            mma16816(oA, awl, bxh[0], bxh[1]);
            mma16816(oB, awh, bxh[2], bxh[3]);
            mma16816(oB, awh, bxl[2], bxl[3]);
            mma16816(oB, awl, bxh[2], bxh[3]);
        }
    }
}

__global__ __launch_bounds__(256) void qkv_mma_kernel(
    const float* __restrict__ bq, const float* __restrict__ bk, const float* __restrict__ bv)
{
    __shared__ __align__(16) char smem[2 * STG];
    int z = blockIdx.z, b = z / 3, which = z % 3;
    const __nv_bfloat16* gwh = g_wh + (size_t)which * 65536;
    const __nv_bfloat16* gwl = g_wl + (size_t)which * 65536;
    const float* bias = (which == 0) ? bq : (which == 1) ? bk : bv;
    __nv_bfloat16* oh = (which == 0) ? g_qh : (which == 1) ? g_kh : g_vh;
    __nv_bfloat16* ol = (which == 0) ? g_ql : (which == 1) ? g_kl : g_vl;
    int m0 = blockIdx.y * 128, s0 = blockIdx.x * 128;
    int tid = threadIdx.x;
    size_t ob = (size_t)b * CH * SP;
    const __nv_bfloat16* xh = g_xh + ob;
    const __nv_bfloat16* xl = g_xl + ob;

    float acc[16][4];
#pragma unroll
    for (int i = 0; i < 16; i++)
#pragma unroll
        for (int j = 0; j < 4; j++) acc[i][j] = 0.0f;

    conv_gemm_body(acc, sm_u32(smem), tid, gwh, gwl, xh, xl, m0, s0);

    int w = tid >> 5, lane = tid & 31;
    int r0 = 16 * w + (lane >> 2), c2 = (lane & 3) * 2;
    float b0 = bias[m0 + r0], b1 = bias[m0 + r0 + 8];
    size_t ro0 = ob + (size_t)(m0 + r0) * SP;
    size_t ro1 = ob + (size_t)(m0 + r0 + 8) * SP;
#pragma unroll
    for (int nt = 0; nt < 8; nt++) {
        int c = s0 + nt * 16 + c2;
        uint32_t hh, ll;
        split2(acc[2 * nt][0] + b0, acc[2 * nt][1] + b0, hh, ll);
        *(uint32_t*)&oh[ro0 + c] = hh;  *(uint32_t*)&ol[ro0 + c] = ll;
        split2(acc[2 * nt][2] + b1, acc[2 * nt][3] + b1, hh, ll);
        *(uint32_t*)&oh[ro1 + c] = hh;  *(uint32_t*)&ol[ro1 + c] = ll;
        split2(acc[2 * nt + 1][0] + b0, acc[2 * nt + 1][1] + b0, hh, ll);
        *(uint32_t*)&oh[ro0 + c + 8] = hh;  *(uint32_t*)&ol[ro0 + c + 8] = ll;
        split2(acc[2 * nt + 1][2] + b1, acc[2 * nt + 1][3] + b1, hh, ll);
        *(uint32_t*)&oh[ro1 + c + 8] = hh;  *(uint32_t*)&ol[ro1 + c + 8] = ll;
    }
}

__global__ __launch_bounds__(256) void out_mma_kernel(
    const float* __restrict__ x, const float* __restrict__ bu, float* __restrict__ out)
{
    __shared__ __align__(16) char smem[2 * STG];
    int b = blockIdx.z;
    const __nv_bfloat16* gwh = g_wh + (size_t)3 * 65536;
    const __nv_bfloat16* gwl = g_wl + (size_t)3 * 65536;
    int m0 = blockIdx.y * 128, s0 = blockIdx.x * 128;
    int tid = threadIdx.x;
    size_t ob = (size_t)b * CH * SP;
    const __nv_bfloat16* ah = g_ah + ob;
    const __nv_bfloat16* al = g_al + ob;

    float acc[16][4];
#pragma unroll
    for (int i = 0; i < 16; i++)
#pragma unroll
        for (int j = 0; j < 4; j++) acc[i][j] = 0.0f;

    conv_gemm_body(acc, sm_u32(smem), tid, gwh, gwl, ah, al, m0, s0);

    int w = tid >> 5, lane = tid & 31;
    int r0 = 16 * w + (lane >> 2), c2 = (lane & 3) * 2;
    float b0 = bu[m0 + r0], b1 = bu[m0 + r0 + 8];
    size_t ro0 = ob + (size_t)(m0 + r0) * SP;
    size_t ro1 = ob + (size_t)(m0 + r0 + 8) * SP;
#pragma unroll
    for (int nt = 0; nt < 8; nt++) {
        int c = s0 + nt * 16 + c2;
        float2 x00 = *(const float2*)&x[ro0 + c];
        float2 x10 = *(const float2*)&x[ro1 + c];
        float2 x01 = *(const float2*)&x[ro0 + c + 8];
        float2 x11 = *(const float2*)&x[ro1 + c + 8];
        float2 v;
        v.x = acc[2 * nt][0] + b0 + x00.x;  v.y = acc[2 * nt][1] + b0 + x00.y;
        *(float2*)&out[ro0 + c] = v;
        v.x = acc[2 * nt][2] + b1 + x10.x;  v.y = acc[2 * nt][3] + b1 + x10.y;
        *(float2*)&out[ro1 + c] = v;
        v.x = acc[2 * nt + 1][0] + b0 + x01.x;  v.y = acc[2 * nt + 1][1] + b0 + x01.y;
        *(float2*)&out[ro0 + c + 8] = v;
        v.x = acc[2 * nt + 1][2] + b1 + x11.x;  v.y = acc[2 * nt + 1][3] + b1 + x11.y;
        *(float2*)&out[ro1 + c + 8] = v;
    }
}

// ---------------------------------------------------------------------------
// Flash attention: Br=64, 128 threads (4 warps x 16 rows), Bc=32.
// 2 CTAs/SM for phase decorrelation. Ql A-fragments live in registers
// (loaded once from gmem); Qh/K/V staged in smem.
// smem: Qh[64][264] + Kh/Kl/Vh/Vl[32][264] = 101376 B
// ---------------------------------------------------------------------------
#define SQ 264
#define ATTN_SMEM ((64 * SQ + 4 * 32 * SQ) * 2)

__global__ __launch_bounds__(128, 2) void attn_kernel()
{
    extern __shared__ __nv_bfloat16 sm[];
    __nv_bfloat16* Qh = sm;
    __nv_bfloat16* Kh = Qh + 64 * SQ;
    __nv_bfloat16* Kl = Kh + 32 * SQ;
    __nv_bfloat16* Vh = Kl + 32 * SQ;
    __nv_bfloat16* Vl = Vh + 32 * SQ;

    int b = blockIdx.y;
    int n0 = blockIdx.x * 64;
    int tid = threadIdx.x;
    int w = tid >> 5, lane = tid & 31;

    size_t base = (size_t)b * CH * SP;
    const uint4* Qgh = (const uint4*)(g_qh + base);
    const uint4* Kgh = (const uint4*)(g_kh + base);
    const uint4* Kgl = (const uint4*)(g_kl + base);
    const uint4* Vgh = (const uint4*)(g_vh + base);
    const uint4* Vgl = (const uint4*)(g_vl + base);

    // cp.async slots: 1024 uint4 per buffer / 128 thr = 8 each
    int lr0 = tid >> 2, lc0 = (tid & 3) * 8;
    uint32_t sKh = sm_u32(Kh), sKl = sm_u32(Kl), sVh = sm_u32(Vh), sVl = sm_u32(Vl);

    // issue K_0
    {
        size_t g = (size_t)lr0 * 32 + lc0;
#pragma unroll
        for (int j = 0; j < 8; j++) {
            uint32_t so = (uint32_t)(lr0 * 33 + lc0 + j) * 16;
            cpa16(sKh + so, Kgh + g + j);
            cpa16(sKl + so, Kgl + g + j);
        }
        cpa_commit();
    }

    // load Qh tile (64 x 256)
    for (int idx = tid; idx < 64 * 32; idx += 128) {
        int r = idx >> 5, c = idx & 31;
        ((uint4*)Qh)[r * 33 + c] = Qgh[(size_t)(n0 + r) * 32 + c];
    }

    // Ql A-fragments direct from gmem into registers (64 regs)
    uint32_t qlf[16][4];
    {
        const __nv_bfloat16* Qlg = g_ql + base;
        int rA = n0 + w * 16 + (lane >> 2);
        int cA = 2 * (lane & 3);
#pragma unroll
        for (int kc = 0; kc < 16; kc++) {
#pragma unroll
            for (int j = 0; j < 4; j++) {
                int r = rA + 8 * (j & 1);
                int c = kc * 16 + cA + 8 * (j >> 1);
                qlf[kc][j] = *(const uint32_t*)&Qlg[(size_t)r * 256 + c];
            }
        }
    }

    int rsel = lane & 15, csel = lane >> 4;
    uint32_t aQh = sm_u32(Qh + (w * 16 + rsel) * SQ + csel * 8);
    uint32_t aKh = sm_u32(Kh + rsel * SQ + csel * 8);
    uint32_t aKl = aKh + 32 * SQ * 2;
    uint32_t aVh = sm_u32(Vh + rsel * SQ + csel * 8);
    uint32_t aVl = aVh + 32 * SQ * 2;

    float o[32][4];
#pragma unroll
    for (int i = 0; i < 32; i++)
#pragma unroll
        for (int j = 0; j < 4; j++) o[i][j] = 0.0f;
    float m0r = -1e30f, m1r = -1e30f, l0r = 0.0f, l1r = 0.0f;

    for (int mt = 0; mt < 128; mt++) {
        cpa_wait_all();
        __syncthreads();

        // issue V_mt
        {
            size_t g = (size_t)(mt * 32 + lr0) * 32 + lc0;
#pragma unroll
            for (int j = 0; j < 8; j++) {
                uint32_t so = (uint32_t)(lr0 * 33 + lc0 + j) * 16;
                cpa16(sVh + so, Vgh + g + j);
                cpa16(sVl + so, Vgl + g + j);
            }
            cpa_commit();
        }

        // ---- S = Q K^T : 16 rows x 32 keys ----
        float s[4][4];
#pragma unroll
        for (int i = 0; i < 4; i++)
#pragma unroll
            for (int j = 0; j < 4; j++) s[i][j] = 0.0f;

#pragma unroll
        for (int kc = 0; kc < 16; kc++) {
            uint32_t ah[4];
            ldsm4(ah, aQh + kc * 32);
#pragma unroll
            for (int np = 0; np < 2; np++) {
                uint32_t bh[4], bl[4];
                ldsm4(bh, aKh + np * (16 * SQ * 2) + kc * 32);
                ldsm4(bl, aKl + np * (16 * SQ * 2) + kc * 32);
                float* sA = s[2 * np];
                float* sB = s[2 * np + 1];
                mma16816(sA, ah, bh[0], bh[2]);
                mma16816(sA, ah, bl[0], bl[2]);
                mma16816(sA, qlf[kc], bh[0], bh[2]);
                mma16816(sB, ah, bh[1], bh[3]);
                mma16816(sB, ah, bl[1], bl[3]);
                mma16816(sB, qlf[kc], bh[1], bh[3]);
            }
        }

        cpa_wait_all();
        __syncthreads();

        // issue K_{mt+1}
        if (mt + 1 < 128) {
            size_t g = (size_t)((mt + 1) * 32 + lr0) * 32 + lc0;
#pragma unroll
            for (int j = 0; j < 8; j++) {
                uint32_t so = (uint32_t)(lr0 * 33 + lc0 + j) * 16;
                cpa16(sKh + so, Kgh + g + j);
                cpa16(sKl + so, Kgl + g + j);
            }
            cpa_commit();
        }

        // ---- softmax ----
        float mx0 = s[0][0], mx1 = s[0][2];
#pragma unroll
        for (int nt = 0; nt < 4; nt++) {
            mx0 = fmaxf(mx0, fmaxf(s[nt][0], s[nt][1]));
            mx1 = fmaxf(mx1, fmaxf(s[nt][2], s[nt][3]));
        }
        mx0 = fmaxf(mx0, __shfl_xor_sync(0xffffffffu, mx0, 1));
        mx0 = fmaxf(mx0, __shfl_xor_sync(0xffffffffu, mx0, 2));
        mx1 = fmaxf(mx1, __shfl_xor_sync(0xffffffffu, mx1, 1));
        mx1 = fmaxf(mx1, __shfl_xor_sync(0xffffffffu, mx1, 2));

        float mn0 = fmaxf(m0r, mx0), mn1 = fmaxf(m1r, mx1);
        float sc0 = __expf(m0r - mn0), sc1 = __expf(m1r - mn1);
        m0r = mn0; m1r = mn1;

        float rs0 = 0.0f, rs1 = 0.0f;
#pragma unroll
        for (int nt = 0; nt < 4; nt++) {
            s[nt][0] = __expf(s[nt][0] - mn0);
            s[nt][1] = __expf(s[nt][1] - mn0);
            s[nt][2] = __expf(s[nt][2] - mn1);
            s[nt][3] = __expf(s[nt][3] - mn1);
            rs0 += s[nt][0] + s[nt][1];
            rs1 += s[nt][2] + s[nt][3];
        }
        rs0 += __shfl_xor_sync(0xffffffffu, rs0, 1);
        rs0 += __shfl_xor_sync(0xffffffffu, rs0, 2);
        rs1 += __shfl_xor_sync(0xffffffffu, rs1, 1);
        rs1 += __shfl_xor_sync(0xffffffffu, rs1, 2);
        l0r = l0r * sc0 + rs0;
        l1r = l1r * sc1 + rs1;

#pragma unroll
        for (int nt = 0; nt < 32; nt++) {
            o[nt][0] *= sc0; o[nt][1] *= sc0;
            o[nt][2] *= sc1; o[nt][3] *= sc1;
        }

        uint32_t ph[2][4], pl[2][4];
#pragma unroll
        for (int kc = 0; kc < 2; kc++) {
            int nt0 = 2 * kc, nt1 = 2 * kc + 1;
            split2(s[nt0][0], s[nt0][1], ph[kc][0], pl[kc][0]);
            split2(s[nt0][2], s[nt0][3], ph[kc][1], pl[kc][1]);
            split2(s[nt1][0], s[nt1][1], ph[kc][2], pl[kc][2]);
            split2(s[nt1][2], s[nt1][3], ph[kc][3], pl[kc][3]);
        }

        // ---- O += P V ----
#pragma unroll
        for (int kc = 0; kc < 2; kc++) {
#pragma unroll
            for (int ct = 0; ct < 16; ct++) {
                uint32_t vh[4], vl[4];
                ldsm4t(vh, aVh + kc * (16 * SQ * 2) + ct * 32);
                ldsm4t(vl, aVl + kc * (16 * SQ * 2) + ct * 32);
                float* oA = o[2 * ct];
                float* oB = o[2 * ct + 1];
                mma16816(oA, ph[kc], vh[0], vh[1]);
                mma16816(oA, ph[kc], vl[0], vl[1]);
                mma16816(oA, pl[kc], vh[0], vh[1]);
                mma16816(oB, ph[kc], vh[2], vh[3]);
                mma16816(oB, ph[kc], vl[2], vl[3]);
                mma16816(oB, pl[kc], vh[2], vh[3]);
            }
        }
    }

    // epilogue: normalize, store bf16 hi/lo to g_ah/g_al
    float inv0 = 1.0f / l0r, inv1 = 1.0f / l1r;
    int r0 = n0 + w * 16 + (lane >> 2);
    int r1 = r0 + 8;
    int cb = (lane & 3) * 2;
#pragma unroll
    for (int nt = 0; nt < 32; nt++) {
        int c = nt * 8 + cb;
        uint32_t hh, ll;
        split2(o[nt][0] * inv0, o[nt][1] * inv0, hh, ll);
        *(uint32_t*)&g_ah[base + (size_t)r0 * 256 + c] = hh;
        *(uint32_t*)&g_al[base + (size_t)r0 * 256 + c] = ll;
        split2(o[nt][2] * inv1, o[nt][3] * inv1, hh, ll);
        *(uint32_t*)&g_ah[base + (size_t)r1 * 256 + c] = hh;
        *(uint32_t*)&g_al[base + (size_t)r1 * 256 + c] = ll;
    }
}

// ---------------------------------------------------------------------------
extern "C" void kernel_launch(void* const* d_in, const int* in_sizes, int n_in,
                              void* d_out, int out_size)
{
    (void)in_sizes; (void)n_in; (void)out_size;
    const float* x  = (const float*)d_in[0];
    const float* Wq = (const float*)d_in[1];
    const float* bq = (const float*)d_in[2];
    const float* Wk = (const float*)d_in[3];
    const float* bk = (const float*)d_in[4];
    const float* Wv = (const float*)d_in[5];
    const float* bv = (const float*)d_in[6];
    const float* Wu = (const float*)d_in[7];
    const float* bu = (const float*)d_in[8];
    float* out = (float*)d_out;

    cudaFuncSetAttribute(attn_kernel, cudaFuncAttributeMaxDynamicSharedMemorySize, ATTN_SMEM);

    splitx_kernel<<<4096, 256>>>(x);
    splitw_kernel<<<256, 256>>>(Wq, Wk, Wv, Wu);
    qkv_mma_kernel<<<dim3(32, 2, 12), 256>>>(bq, bk, bv);
    attn_kernel<<<dim3(64, 4), 128, ATTN_SMEM>>>();
    out_mma_kernel<<<dim3(32, 2, 4), 256>>>(x, bu, out);
}

// round 12
// speedup vs baseline: 1.3188x; 1.3188x over previous
#include <cuda_runtime.h>
#include <cuda_bf16.h>
#include <cstdint>

#define BATCH 4
#define CH    256
#define SP    4096
#define DH    256

__device__ __align__(16) __nv_bfloat16 g_xh[BATCH * CH * SP];
__device__ __align__(16) __nv_bfloat16 g_xl[BATCH * CH * SP];
__device__ __align__(16) __nv_bfloat16 g_wh[4 * 65536];
__device__ __align__(16) __nv_bfloat16 g_wl[4 * 65536];
__device__ __align__(16) __nv_bfloat16 g_qh[BATCH * CH * SP];
__device__ __align__(16) __nv_bfloat16 g_ql[BATCH * CH * SP];
__device__ __align__(16) __nv_bfloat16 g_kh[BATCH * CH * SP];
__device__ __align__(16) __nv_bfloat16 g_kl[BATCH * CH * SP];
__device__ __align__(16) __nv_bfloat16 g_vh[BATCH * CH * SP];
__device__ __align__(16) __nv_bfloat16 g_vl[BATCH * CH * SP];
__device__ __align__(16) __nv_bfloat16 g_ah[BATCH * CH * SP];
__device__ __align__(16) __nv_bfloat16 g_al[BATCH * CH * SP];

// ---------------- helpers ----------------
__device__ __forceinline__ uint32_t pk(float x0, float x1) {
    uint32_t r;
    asm("cvt.rn.bf16x2.f32 %0, %1, %2;" : "=r"(r) : "f"(x1), "f"(x0));
    return r;
}
__device__ __forceinline__ void split2(float x0, float x1, uint32_t& hi, uint32_t& lo) {
    float h0 = __bfloat162float(__float2bfloat16(x0));
    float h1 = __bfloat162float(__float2bfloat16(x1));
    hi = pk(x0, x1);
    lo = pk(x0 - h0, x1 - h1);
}
__device__ __forceinline__ void ldsm4(uint32_t* r, uint32_t a) {
    asm volatile("ldmatrix.sync.aligned.m8n8.x4.shared.b16 {%0,%1,%2,%3}, [%4];"
                 : "=r"(r[0]), "=r"(r[1]), "=r"(r[2]), "=r"(r[3]) : "r"(a));
}
__device__ __forceinline__ void ldsm4t(uint32_t* r, uint32_t a) {
    asm volatile("ldmatrix.sync.aligned.m8n8.x4.trans.shared.b16 {%0,%1,%2,%3}, [%4];"
                 : "=r"(r[0]), "=r"(r[1]), "=r"(r[2]), "=r"(r[3]) : "r"(a));
}
__device__ __forceinline__ void mma16816(float* d, const uint32_t* a, uint32_t b0, uint32_t b1) {
    asm volatile("mma.sync.aligned.m16n8k16.row.col.f32.bf16.bf16.f32 "
                 "{%0,%1,%2,%3}, {%4,%5,%6,%7}, {%8,%9}, {%0,%1,%2,%3};"
                 : "+f"(d[0]), "+f"(d[1]), "+f"(d[2]), "+f"(d[3])
                 : "r"(a[0]), "r"(a[1]), "r"(a[2]), "r"(a[3]), "r"(b0), "r"(b1));
}
__device__ __forceinline__ uint32_t sm_u32(const void* p) {
    return (uint32_t)__cvta_generic_to_shared(p);
}
__device__ __forceinline__ void cpa16(uint32_t dst, const void* src) {
    asm volatile("cp.async.cg.shared.global [%0], [%1], 16;" :: "r"(dst), "l"(src));
}
__device__ __forceinline__ void cpa_commit() { asm volatile("cp.async.commit_group;"); }
__device__ __forceinline__ void cpa_wait_all() { asm volatile("cp.async.wait_group 0;"); }

// ---------------------------------------------------------------------------
// Split kernels: fp32 -> bf16 hi/lo
// ---------------------------------------------------------------------------
__global__ __launch_bounds__(256) void splitx_kernel(const float* __restrict__ x)
{
    size_t i = ((size_t)blockIdx.x * 256 + threadIdx.x) * 4;
    float4 v = *(const float4*)(x + i);
    uint32_t h0, l0, h1, l1;
    split2(v.x, v.y, h0, l0);
    split2(v.z, v.w, h1, l1);
    uint2 hw, lw;
    hw.x = h0; hw.y = h1; lw.x = l0; lw.y = l1;
    *(uint2*)&g_xh[i] = hw;
    *(uint2*)&g_xl[i] = lw;
}

__global__ __launch_bounds__(256) void splitw_kernel(
    const float* __restrict__ Wq, const float* __restrict__ Wk,
    const float* __restrict__ Wv, const float* __restrict__ Wu)
{
    size_t i = ((size_t)blockIdx.x * 256 + threadIdx.x) * 4;
    int which = (int)(i >> 16);
    const float* W = (which == 0) ? Wq : (which == 1) ? Wk : (which == 2) ? Wv : Wu;
    float4 v = *(const float4*)(W + (i & 65535));
    uint32_t h0, l0, h1, l1;
    split2(v.x, v.y, h0, l0);
    split2(v.z, v.w, h1, l1);
    uint2 hw, lw;
    hw.x = h0; hw.y = h1; lw.x = l0; lw.y = l1;
    *(uint2*)&g_wh[i] = hw;
    *(uint2*)&g_wl[i] = lw;
}

// ---------------------------------------------------------------------------
// Conv GEMM on tensor cores (bf16 hi/lo, 3-term). CTA: 128(out-ch) x 128(sp).
// ---------------------------------------------------------------------------
#define STG 21504
#define WL_OFF 6144
#define XH_OFF 12288
#define XL_OFF 16640

__device__ __forceinline__ void conv_issue(
    uint32_t sb, int tid, int kc,
    const __nv_bfloat16* gwh, const __nv_bfloat16* gwl,
    const __nv_bfloat16* xh, const __nv_bfloat16* xl,
    int m0, int s0)
{
    int mm = tid & 127, g = tid >> 7;
    const __nv_bfloat16* swh = gwh + (size_t)(m0 + mm) * 256 + kc * 16 + g * 8;
    const __nv_bfloat16* swl = gwl + (size_t)(m0 + mm) * 256 + kc * 16 + g * 8;
    cpa16(sb + mm * 48 + g * 16, swh);
    cpa16(sb + WL_OFF + mm * 48 + g * 16, swl);
    int kk = tid >> 4, sg = (tid & 15) * 8;
    const __nv_bfloat16* sxh = xh + (size_t)(kc * 16 + kk) * SP + s0 + sg;
    const __nv_bfloat16* sxl = xl + (size_t)(kc * 16 + kk) * SP + s0 + sg;
    cpa16(sb + XH_OFF + kk * 272 + sg * 2, sxh);
    cpa16(sb + XL_OFF + kk * 272 + sg * 2, sxl);
}

__device__ __forceinline__ void conv_gemm_body(
    float acc[16][4], uint32_t smb, int tid,
    const __nv_bfloat16* gwh, const __nv_bfloat16* gwl,
    const __nv_bfloat16* xh, const __nv_bfloat16* xl,
    int m0, int s0)
{
    int w = tid >> 5, lane = tid & 31;
    int rsel = lane & 15, csel = lane >> 4;

    conv_issue(smb, tid, 0, gwh, gwl, xh, xl, m0, s0);
    cpa_commit();

    for (int kc = 0; kc < 16; kc++) {
        cpa_wait_all();
        __syncthreads();
        if (kc < 15) {
            conv_issue(smb + ((kc + 1) & 1) * STG, tid, kc + 1, gwh, gwl, xh, xl, m0, s0);
            cpa_commit();
        }
        uint32_t base = smb + (kc & 1) * STG;
        uint32_t aW  = base + (16 * w + rsel) * 48 + csel * 16;
        uint32_t aWl = aW + WL_OFF;
        uint32_t aX  = base + XH_OFF + rsel * 272 + csel * 16;
        uint32_t aXl = aX + (XL_OFF - XH_OFF);

        uint32_t awh[4], awl[4];
        ldsm4(awh, aW);
        ldsm4(awl, aWl);
#pragma unroll
        for (int nt = 0; nt < 8; nt++) {
            uint32_t bxh[4], bxl[4];
            ldsm4t(bxh, aX + nt * 32);
            ldsm4t(bxl, aXl + nt * 32);
            float* oA = acc[2 * nt];
            float* oB = acc[2 * nt + 1];
            mma16816(oA, awh, bxh[0], bxh[1]);
            mma16816(oA, awh, bxl[0], bxl[1]);
            mma16816(oA, awl, bxh[0], bxh[1]);
            mma16816(oB, awh, bxh[2], bxh[3]);
            mma16816(oB, awh, bxl[2], bxl[3]);
            mma16816(oB, awl, bxh[2], bxh[3]);
        }
    }
}

__global__ __launch_bounds__(256) void qkv_mma_kernel(
    const float* __restrict__ bq, const float* __restrict__ bk, const float* __restrict__ bv)
{
    __shared__ __align__(16) char smem[2 * STG];
    int z = blockIdx.z, b = z / 3, which = z % 3;
    const __nv_bfloat16* gwh = g_wh + (size_t)which * 65536;
    const __nv_bfloat16* gwl = g_wl + (size_t)which * 65536;
    const float* bias = (which == 0) ? bq : (which == 1) ? bk : bv;
    __nv_bfloat16* oh = (which == 0) ? g_qh : (which == 1) ? g_kh : g_vh;
    __nv_bfloat16* ol = (which == 0) ? g_ql : (which == 1) ? g_kl : g_vl;
    int m0 = blockIdx.y * 128, s0 = blockIdx.x * 128;
    int tid = threadIdx.x;
    size_t ob = (size_t)b * CH * SP;
    const __nv_bfloat16* xh = g_xh + ob;
    const __nv_bfloat16* xl = g_xl + ob;

    float acc[16][4];
#pragma unroll
    for (int i = 0; i < 16; i++)
#pragma unroll
        for (int j = 0; j < 4; j++) acc[i][j] = 0.0f;

    conv_gemm_body(acc, sm_u32(smem), tid, gwh, gwl, xh, xl, m0, s0);

    int w = tid >> 5, lane = tid & 31;
    int r0 = 16 * w + (lane >> 2), c2 = (lane & 3) * 2;
    float b0 = bias[m0 + r0], b1 = bias[m0 + r0 + 8];
    size_t ro0 = ob + (size_t)(m0 + r0) * SP;
    size_t ro1 = ob + (size_t)(m0 + r0 + 8) * SP;
#pragma unroll
    for (int nt = 0; nt < 8; nt++) {
        int c = s0 + nt * 16 + c2;
        uint32_t hh, ll;
        split2(acc[2 * nt][0] + b0, acc[2 * nt][1] + b0, hh, ll);
        *(uint32_t*)&oh[ro0 + c] = hh;  *(uint32_t*)&ol[ro0 + c] = ll;
        split2(acc[2 * nt][2] + b1, acc[2 * nt][3] + b1, hh, ll);
        *(uint32_t*)&oh[ro1 + c] = hh;  *(uint32_t*)&ol[ro1 + c] = ll;
        split2(acc[2 * nt + 1][0] + b0, acc[2 * nt + 1][1] + b0, hh, ll);
        *(uint32_t*)&oh[ro0 + c + 8] = hh;  *(uint32_t*)&ol[ro0 + c + 8] = ll;
        split2(acc[2 * nt + 1][2] + b1, acc[2 * nt + 1][3] + b1, hh, ll);
        *(uint32_t*)&oh[ro1 + c + 8] = hh;  *(uint32_t*)&ol[ro1 + c + 8] = ll;
    }
}

__global__ __launch_bounds__(256) void out_mma_kernel(
    const float* __restrict__ x, const float* __restrict__ bu, float* __restrict__ out)
{
    __shared__ __align__(16) char smem[2 * STG];
    int b = blockIdx.z;
    const __nv_bfloat16* gwh = g_wh + (size_t)3 * 65536;
    const __nv_bfloat16* gwl = g_wl + (size_t)3 * 65536;
    int m0 = blockIdx.y * 128, s0 = blockIdx.x * 128;
    int tid = threadIdx.x;
    size_t ob = (size_t)b * CH * SP;
    const __nv_bfloat16* ah = g_ah + ob;
    const __nv_bfloat16* al = g_al + ob;

    float acc[16][4];
#pragma unroll
    for (int i = 0; i < 16; i++)
#pragma unroll
        for (int j = 0; j < 4; j++) acc[i][j] = 0.0f;

    conv_gemm_body(acc, sm_u32(smem), tid, gwh, gwl, ah, al, m0, s0);

    int w = tid >> 5, lane = tid & 31;
    int r0 = 16 * w + (lane >> 2), c2 = (lane & 3) * 2;
    float b0 = bu[m0 + r0], b1 = bu[m0 + r0 + 8];
    size_t ro0 = ob + (size_t)(m0 + r0) * SP;
    size_t ro1 = ob + (size_t)(m0 + r0 + 8) * SP;
#pragma unroll
    for (int nt = 0; nt < 8; nt++) {
        int c = s0 + nt * 16 + c2;
        float2 x00 = *(const float2*)&x[ro0 + c];
        float2 x10 = *(const float2*)&x[ro1 + c];
        float2 x01 = *(const float2*)&x[ro0 + c + 8];
        float2 x11 = *(const float2*)&x[ro1 + c + 8];
        float2 v;
        v.x = acc[2 * nt][0] + b0 + x00.x;  v.y = acc[2 * nt][1] + b0 + x00.y;
        *(float2*)&out[ro0 + c] = v;
        v.x = acc[2 * nt][2] + b1 + x10.x;  v.y = acc[2 * nt][3] + b1 + x10.y;
        *(float2*)&out[ro1 + c] = v;
        v.x = acc[2 * nt + 1][0] + b0 + x01.x;  v.y = acc[2 * nt + 1][1] + b0 + x01.y;
        *(float2*)&out[ro0 + c + 8] = v;
        v.x = acc[2 * nt + 1][2] + b1 + x11.x;  v.y = acc[2 * nt + 1][3] + b1 + x11.y;
        *(float2*)&out[ro1 + c + 8] = v;
    }
}

// ---------------------------------------------------------------------------
// Flash attention: Br=128, 256 thr, 8 warps, 1 CTA/SM.
// Deferred-PV pipeline: iter t computes S_t, then softmax_t (ALU) overlapped
// with O += P_{t-1} V_{t-1} (tensor). P carried in regs, V double-buffered,
// Ql A-fragments register-resident.
// smem: Qh[128][264] + Kh/Kl[32][264] + V[2][hi/lo][32][264] = 168960 B
// ---------------------------------------------------------------------------
#define SQ 264
#define ATTN_SMEM ((128 * SQ + 6 * 32 * SQ) * 2)

__global__ __launch_bounds__(256, 1) void attn_kernel()
{
    extern __shared__ __nv_bfloat16 sm[];
    __nv_bfloat16* Qh = sm;
    __nv_bfloat16* Kh = Qh + 128 * SQ;
    __nv_bfloat16* Kl = Kh + 32 * SQ;
    __nv_bfloat16* Vb = Kl + 32 * SQ;   // [parity][hi/lo][32][SQ]

    int b = blockIdx.y;
    int n0 = blockIdx.x * 128;
    int tid = threadIdx.x;
    int w = tid >> 5, lane = tid & 31;

    size_t base = (size_t)b * CH * SP;
    const uint4* Qgh = (const uint4*)(g_qh + base);
    const uint4* Kgh = (const uint4*)(g_kh + base);
    const uint4* Kgl = (const uint4*)(g_kl + base);
    const uint4* Vgh = (const uint4*)(g_vh + base);
    const uint4* Vgl = (const uint4*)(g_vl + base);

    int lr0 = tid >> 3, lc0 = (tid & 7) * 4;
    uint32_t sKh = sm_u32(Kh), sKl = sm_u32(Kl);
    uint32_t sVb = sm_u32(Vb);

    // issue K_0
    {
        size_t g = (size_t)lr0 * 32 + lc0;
        uint32_t s = (uint32_t)(lr0 * 33 + lc0) * 16;
#pragma unroll
        for (int j = 0; j < 4; j++) {
            cpa16(sKh + s + j * 16, Kgh + g + j);
            cpa16(sKl + s + j * 16, Kgl + g + j);
        }
        cpa_commit();
    }

    // load Qh tile
    for (int idx = tid; idx < 128 * 32; idx += 256) {
        int r = idx >> 5, c = idx & 31;
        ((uint4*)Qh)[r * 33 + c] = Qgh[(size_t)(n0 + r) * 32 + c];
    }

    // Ql A-fragments (register-resident, validated in R11)
    uint32_t qlf[16][4];
    {
        const __nv_bfloat16* Qlg = g_ql + base;
        int rA = n0 + w * 16 + (lane >> 2);
        int cA = 2 * (lane & 3);
#pragma unroll
        for (int kc = 0; kc < 16; kc++) {
#pragma unroll
            for (int j = 0; j < 4; j++) {
                int r = rA + 8 * (j & 1);
                int c = kc * 16 + cA + 8 * (j >> 1);
                qlf[kc][j] = *(const uint32_t*)&Qlg[(size_t)r * 256 + c];
            }
        }
    }

    int rsel = lane & 15, csel = lane >> 4;
    uint32_t aQh = sm_u32(Qh + (w * 16 + rsel) * SQ + csel * 8);
    uint32_t aKh = sKh + (rsel * SQ + csel * 8) * 2;
    uint32_t aKl = aKh + 32 * SQ * 2;
    uint32_t aVf = sVb + (rsel * SQ + csel * 8) * 2;

    float o[32][4];
#pragma unroll
    for (int i = 0; i < 32; i++)
#pragma unroll
        for (int j = 0; j < 4; j++) o[i][j] = 0.0f;
    float m0r = -1e30f, m1r = -1e30f, l0r = 0.0f, l1r = 0.0f;
    uint32_t php[2][4], plp[2][4];   // P_{t-1} carry

    for (int mt = 0; mt < 128; mt++) {
        cpa_wait_all();      // K_mt and V_{mt-1} complete
        __syncthreads();

        // issue V_mt into parity mt&1
        {
            size_t g = (size_t)(mt * 32 + lr0) * 32 + lc0;
            uint32_t vdst = sVb + (uint32_t)(mt & 1) * (2 * 32 * SQ * 2) + (uint32_t)(lr0 * 33 + lc0) * 16;
#pragma unroll
            for (int j = 0; j < 4; j++) {
                cpa16(vdst + j * 16, Vgh + g + j);
                cpa16(vdst + 32 * SQ * 2 + j * 16, Vgl + g + j);
            }
            cpa_commit();
        }

        // ---- S_mt = Q K^T ----
        float s[4][4];
#pragma unroll
        for (int i = 0; i < 4; i++)
#pragma unroll
            for (int j = 0; j < 4; j++) s[i][j] = 0.0f;

#pragma unroll
        for (int kc = 0; kc < 16; kc++) {
            uint32_t ah[4];
            ldsm4(ah, aQh + kc * 32);
#pragma unroll
            for (int np = 0; np < 2; np++) {
                uint32_t bh[4], bl[4];
                ldsm4(bh, aKh + np * (16 * SQ * 2) + kc * 32);
                ldsm4(bl, aKl + np * (16 * SQ * 2) + kc * 32);
                float* sA = s[2 * np];
                float* sB = s[2 * np + 1];
                mma16816(sA, ah, bh[0], bh[2]);
                mma16816(sA, ah, bl[0], bl[2]);
                mma16816(sA, qlf[kc], bh[0], bh[2]);
                mma16816(sB, ah, bh[1], bh[3]);
                mma16816(sB, ah, bl[1], bl[3]);
                mma16816(sB, qlf[kc], bh[1], bh[3]);
            }
        }

        __syncthreads();     // all warps done reading K_mt

        // issue K_{mt+1}
        if (mt + 1 < 128) {
            size_t g = (size_t)((mt + 1) * 32 + lr0) * 32 + lc0;
            uint32_t s2 = (uint32_t)(lr0 * 33 + lc0) * 16;
#pragma unroll
            for (int j = 0; j < 4; j++) {
                cpa16(sKh + s2 + j * 16, Kgh + g + j);
                cpa16(sKl + s2 + j * 16, Kgl + g + j);
            }
            cpa_commit();
        }

        // ---- softmax_mt (ALU) overlapped with PV_{mt-1} (tensor) ----
        float mx0 = s[0][0], mx1 = s[0][2];
#pragma unroll
        for (int nt = 0; nt < 4; nt++) {
            mx0 = fmaxf(mx0, fmaxf(s[nt][0], s[nt][1]));
            mx1 = fmaxf(mx1, fmaxf(s[nt][2], s[nt][3]));
        }
        mx0 = fmaxf(mx0, __shfl_xor_sync(0xffffffffu, mx0, 1));
        mx0 = fmaxf(mx0, __shfl_xor_sync(0xffffffffu, mx0, 2));
        mx1 = fmaxf(mx1, __shfl_xor_sync(0xffffffffu, mx1, 1));
        mx1 = fmaxf(mx1, __shfl_xor_sync(0xffffffffu, mx1, 2));

        float mn0 = fmaxf(m0r, mx0), mn1 = fmaxf(m1r, mx1);
        float sc0 = __expf(m0r - mn0), sc1 = __expf(m1r - mn1);
        m0r = mn0; m1r = mn1;

#pragma unroll
        for (int nt = 0; nt < 4; nt++) {
            s[nt][0] = __expf(s[nt][0] - mn0);
            s[nt][1] = __expf(s[nt][1] - mn0);
            s[nt][2] = __expf(s[nt][2] - mn1);
            s[nt][3] = __expf(s[nt][3] - mn1);
        }

        // PV_{mt-1}: tensor work filling the softmax ALU window
        if (mt > 0) {
            uint32_t aV = aVf + (uint32_t)((mt - 1) & 1) * (2 * 32 * SQ * 2);
            uint32_t aVl2 = aV + 32 * SQ * 2;
#pragma unroll
            for (int kc = 0; kc < 2; kc++) {
#pragma unroll
                for (int ct = 0; ct < 16; ct++) {
                    uint32_t vh[4], vl[4];
                    ldsm4t(vh, aV + kc * (16 * SQ * 2) + ct * 32);
                    ldsm4t(vl, aVl2 + kc * (16 * SQ * 2) + ct * 32);
                    float* oA = o[2 * ct];
                    float* oB = o[2 * ct + 1];
                    mma16816(oA, php[kc], vh[0], vh[1]);
                    mma16816(oA, php[kc], vl[0], vl[1]);
                    mma16816(oA, plp[kc], vh[0], vh[1]);
                    mma16816(oB, php[kc], vh[2], vh[3]);
                    mma16816(oB, php[kc], vl[2], vl[3]);
                    mma16816(oB, plp[kc], vh[2], vh[3]);
                }
            }
        }

        // row sums + l update
        float rs0 = s[0][0] + s[0][1] + s[1][0] + s[1][1] + s[2][0] + s[2][1] + s[3][0] + s[3][1];
        float rs1 = s[0][2] + s[0][3] + s[1][2] + s[1][3] + s[2][2] + s[2][3] + s[3][2] + s[3][3];
        rs0 += __shfl_xor_sync(0xffffffffu, rs0, 1);
        rs0 += __shfl_xor_sync(0xffffffffu, rs0, 2);
        rs1 += __shfl_xor_sync(0xffffffffu, rs1, 1);
        rs1 += __shfl_xor_sync(0xffffffffu, rs1, 2);
        l0r = l0r * sc0 + rs0;
        l1r = l1r * sc1 + rs1;

        // O rescale to m_mt (after PV_{mt-1} was added in old scale)
#pragma unroll
        for (int nt = 0; nt < 32; nt++) {
            o[nt][0] *= sc0; o[nt][1] *= sc0;
            o[nt][2] *= sc1; o[nt][3] *= sc1;
        }

        // carry P_mt
#pragma unroll
        for (int kc = 0; kc < 2; kc++) {
            int nt0 = 2 * kc, nt1 = 2 * kc + 1;
            split2(s[nt0][0], s[nt0][1], php[kc][0], plp[kc][0]);
            split2(s[nt0][2], s[nt0][3], php[kc][1], plp[kc][1]);
            split2(s[nt1][0], s[nt1][1], php[kc][2], plp[kc][2]);
            split2(s[nt1][2], s[nt1][3], php[kc][3], plp[kc][3]);
        }
    }

    // final PV_127
    cpa_wait_all();
    __syncthreads();
    {
        uint32_t aV = aVf + (uint32_t)(127 & 1) * (2 * 32 * SQ * 2);
        uint32_t aVl2 = aV + 32 * SQ * 2;
#pragma unroll
        for (int kc = 0; kc < 2; kc++) {
#pragma unroll
            for (int ct = 0; ct < 16; ct++) {
                uint32_t vh[4], vl[4];
                ldsm4t(vh, aV + kc * (16 * SQ * 2) + ct * 32);
                ldsm4t(vl, aVl2 + kc * (16 * SQ * 2) + ct * 32);
                float* oA = o[2 * ct];
                float* oB = o[2 * ct + 1];
                mma16816(oA, php[kc], vh[0], vh[1]);
                mma16816(oA, php[kc], vl[0], vl[1]);
                mma16816(oA, plp[kc], vh[0], vh[1]);
                mma16816(oB, php[kc], vh[2], vh[3]);
                mma16816(oB, php[kc], vl[2], vl[3]);
                mma16816(oB, plp[kc], vh[2], vh[3]);
            }
        }
    }

    // epilogue: normalize, store bf16 hi/lo
    float inv0 = 1.0f / l0r, inv1 = 1.0f / l1r;
    int r0 = n0 + w * 16 + (lane >> 2);
    int r1 = r0 + 8;
    int cb = (lane & 3) * 2;
#pragma unroll
    for (int nt = 0; nt < 32; nt++) {
        int c = nt * 8 + cb;
        uint32_t hh, ll;
        split2(o[nt][0] * inv0, o[nt][1] * inv0, hh, ll);
        *(uint32_t*)&g_ah[base + (size_t)r0 * 256 + c] = hh;
        *(uint32_t*)&g_al[base + (size_t)r0 * 256 + c] = ll;
        split2(o[nt][2] * inv1, o[nt][3] * inv1, hh, ll);
        *(uint32_t*)&g_ah[base + (size_t)r1 * 256 + c] = hh;
        *(uint32_t*)&g_al[base + (size_t)r1 * 256 + c] = ll;
    }
}

// ---------------------------------------------------------------------------
extern "C" void kernel_launch(void* const* d_in, const int* in_sizes, int n_in,
                              void* d_out, int out_size)
{
    (void)in_sizes; (void)n_in; (void)out_size;
    const float* x  = (const float*)d_in[0];
    const float* Wq = (const float*)d_in[1];
    const float* bq = (const float*)d_in[2];
    const float* Wk = (const float*)d_in[3];
    const float* bk = (const float*)d_in[4];
    const float* Wv = (const float*)d_in[5];
    const float* bv = (const float*)d_in[6];
    const float* Wu = (const float*)d_in[7];
    const float* bu = (const float*)d_in[8];
    float* out = (float*)d_out;

    cudaFuncSetAttribute(attn_kernel, cudaFuncAttributeMaxDynamicSharedMemorySize, ATTN_SMEM);

    splitx_kernel<<<4096, 256>>>(x);
    splitw_kernel<<<256, 256>>>(Wq, Wk, Wv, Wu);
    qkv_mma_kernel<<<dim3(32, 2, 12), 256>>>(bq, bk, bv);
    attn_kernel<<<dim3(32, 4), 256, ATTN_SMEM>>>();
    out_mma_kernel<<<dim3(32, 2, 4), 256>>>(x, bu, out);
}

// round 13
// speedup vs baseline: 1.3390x; 1.0153x over previous
#include <cuda_runtime.h>
#include <cuda_bf16.h>
#include <cstdint>

#define BATCH 4
#define CH    256
#define SP    4096
#define DH    256

__device__ __align__(16) __nv_bfloat16 g_xh[BATCH * CH * SP];
__device__ __align__(16) __nv_bfloat16 g_xl[BATCH * CH * SP];
__device__ __align__(16) __nv_bfloat16 g_wh[4 * 65536];
__device__ __align__(16) __nv_bfloat16 g_wl[4 * 65536];
__device__ __align__(16) __nv_bfloat16 g_qh[BATCH * CH * SP];
__device__ __align__(16) __nv_bfloat16 g_ql[BATCH * CH * SP];
__device__ __align__(16) __nv_bfloat16 g_kh[BATCH * CH * SP];
__device__ __align__(16) __nv_bfloat16 g_kl[BATCH * CH * SP];
__device__ __align__(16) __nv_bfloat16 g_vh[BATCH * CH * SP];
__device__ __align__(16) __nv_bfloat16 g_vl[BATCH * CH * SP];
__device__ __align__(16) __nv_bfloat16 g_ah[BATCH * CH * SP];
__device__ __align__(16) __nv_bfloat16 g_al[BATCH * CH * SP];

// ---------------- helpers ----------------
__device__ __forceinline__ uint32_t pk(float x0, float x1) {
    uint32_t r;
    asm("cvt.rn.bf16x2.f32 %0, %1, %2;" : "=r"(r) : "f"(x1), "f"(x0));
    return r;
}
__device__ __forceinline__ void split2(float x0, float x1, uint32_t& hi, uint32_t& lo) {
    float h0 = __bfloat162float(__float2bfloat16(x0));
    float h1 = __bfloat162float(__float2bfloat16(x1));
    hi = pk(x0, x1);
    lo = pk(x0 - h0, x1 - h1);
}
__device__ __forceinline__ void ldsm4(uint32_t* r, uint32_t a) {
    asm volatile("ldmatrix.sync.aligned.m8n8.x4.shared.b16 {%0,%1,%2,%3}, [%4];"
                 : "=r"(r[0]), "=r"(r[1]), "=r"(r[2]), "=r"(r[3]) : "r"(a));
}
__device__ __forceinline__ void ldsm4t(uint32_t* r, uint32_t a) {
    asm volatile("ldmatrix.sync.aligned.m8n8.x4.trans.shared.b16 {%0,%1,%2,%3}, [%4];"
                 : "=r"(r[0]), "=r"(r[1]), "=r"(r[2]), "=r"(r[3]) : "r"(a));
}
__device__ __forceinline__ void mma16816(float* d, const uint32_t* a, uint32_t b0, uint32_t b1) {
    asm volatile("mma.sync.aligned.m16n8k16.row.col.f32.bf16.bf16.f32 "
                 "{%0,%1,%2,%3}, {%4,%5,%6,%7}, {%8,%9}, {%0,%1,%2,%3};"
                 : "+f"(d[0]), "+f"(d[1]), "+f"(d[2]), "+f"(d[3])
                 : "r"(a[0]), "r"(a[1]), "r"(a[2]), "r"(a[3]), "r"(b0), "r"(b1));
}
__device__ __forceinline__ uint32_t sm_u32(const void* p) {
    return (uint32_t)__cvta_generic_to_shared(p);
}
__device__ __forceinline__ void cpa16(uint32_t dst, const void* src) {
    asm volatile("cp.async.cg.shared.global [%0], [%1], 16;" :: "r"(dst), "l"(src));
}
__device__ __forceinline__ void cpa_commit() { asm volatile("cp.async.commit_group;"); }
__device__ __forceinline__ void cpa_wait_all() { asm volatile("cp.async.wait_group 0;"); }

// ---------------------------------------------------------------------------
// Split kernels: fp32 -> bf16 hi/lo
// ---------------------------------------------------------------------------
__global__ __launch_bounds__(256) void splitx_kernel(const float* __restrict__ x)
{
    size_t i = ((size_t)blockIdx.x * 256 + threadIdx.x) * 4;
    float4 v = *(const float4*)(x + i);
    uint32_t h0, l0, h1, l1;
    split2(v.x, v.y, h0, l0);
    split2(v.z, v.w, h1, l1);
    uint2 hw, lw;
    hw.x = h0; hw.y = h1; lw.x = l0; lw.y = l1;
    *(uint2*)&g_xh[i] = hw;
    *(uint2*)&g_xl[i] = lw;
}

__global__ __launch_bounds__(256) void splitw_kernel(
    const float* __restrict__ Wq, const float* __restrict__ Wk,
    const float* __restrict__ Wv, const float* __restrict__ Wu)
{
    size_t i = ((size_t)blockIdx.x * 256 + threadIdx.x) * 4;
    int which = (int)(i >> 16);
    const float* W = (which == 0) ? Wq : (which == 1) ? Wk : (which == 2) ? Wv : Wu;
    float4 v = *(const float4*)(W + (i & 65535));
    uint32_t h0, l0, h1, l1;
    split2(v.x, v.y, h0, l0);
    split2(v.z, v.w, h1, l1);
    uint2 hw, lw;
    hw.x = h0; hw.y = h1; lw.x = l0; lw.y = l1;
    *(uint2*)&g_wh[i] = hw;
    *(uint2*)&g_wl[i] = lw;
}

// ---------------------------------------------------------------------------
// Conv GEMM on tensor cores (bf16 hi/lo, 3-term). CTA: 128(out-ch) x 128(sp).
// ---------------------------------------------------------------------------
#define STG 21504
#define WL_OFF 6144
#define XH_OFF 12288
#define XL_OFF 16640

__device__ __forceinline__ void conv_issue(
    uint32_t sb, int tid, int kc,
    const __nv_bfloat16* gwh, const __nv_bfloat16* gwl,
    const __nv_bfloat16* xh, const __nv_bfloat16* xl,
    int m0, int s0)
{
    int mm = tid & 127, g = tid >> 7;
    const __nv_bfloat16* swh = gwh + (size_t)(m0 + mm) * 256 + kc * 16 + g * 8;
    const __nv_bfloat16* swl = gwl + (size_t)(m0 + mm) * 256 + kc * 16 + g * 8;
    cpa16(sb + mm * 48 + g * 16, swh);
    cpa16(sb + WL_OFF + mm * 48 + g * 16, swl);
    int kk = tid >> 4, sg = (tid & 15) * 8;
    const __nv_bfloat16* sxh = xh + (size_t)(kc * 16 + kk) * SP + s0 + sg;
    const __nv_bfloat16* sxl = xl + (size_t)(kc * 16 + kk) * SP + s0 + sg;
    cpa16(sb + XH_OFF + kk * 272 + sg * 2, sxh);
    cpa16(sb + XL_OFF + kk * 272 + sg * 2, sxl);
}

__device__ __forceinline__ void conv_gemm_body(
    float acc[16][4], uint32_t smb, int tid,
    const __nv_bfloat16* gwh, const __nv_bfloat16* gwl,
    const __nv_bfloat16* xh, const __nv_bfloat16* xl,
    int m0, int s0)
{
    int w = tid >> 5, lane = tid & 31;
    int rsel = lane & 15, csel = lane >> 4;

    conv_issue(smb, tid, 0, gwh, gwl, xh, xl, m0, s0);
    cpa_commit();

    for (int kc = 0; kc < 16; kc++) {
        cpa_wait_all();
        __syncthreads();
        if (kc < 15) {
            conv_issue(smb + ((kc + 1) & 1) * STG, tid, kc + 1, gwh, gwl, xh, xl, m0, s0);
            cpa_commit();
        }
        uint32_t base = smb + (kc & 1) * STG;
        uint32_t aW  = base + (16 * w + rsel) * 48 + csel * 16;
        uint32_t aWl = aW + WL_OFF;
        uint32_t aX  = base + XH_OFF + rsel * 272 + csel * 16;
        uint32_t aXl = aX + (XL_OFF - XH_OFF);

        uint32_t awh[4], awl[4];
        ldsm4(awh, aW);
        ldsm4(awl, aWl);
#pragma unroll
        for (int nt = 0; nt < 8; nt++) {
            uint32_t bxh[4], bxl[4];
            ldsm4t(bxh, aX + nt * 32);
            ldsm4t(bxl, aXl + nt * 32);
            float* oA = acc[2 * nt];
            float* oB = acc[2 * nt + 1];
            mma16816(oA, awh, bxh[0], bxh[1]);
            mma16816(oB, awh, bxh[2], bxh[3]);
            mma16816(oA, awh, bxl[0], bxl[1]);
            mma16816(oB, awh, bxl[2], bxl[3]);
            mma16816(oA, awl, bxh[0], bxh[1]);
            mma16816(oB, awl, bxh[2], bxh[3]);
        }
    }
}

__global__ __launch_bounds__(256) void qkv_mma_kernel(
    const float* __restrict__ bq, const float* __restrict__ bk, const float* __restrict__ bv)
{
    __shared__ __align__(16) char smem[2 * STG];
    int z = blockIdx.z, b = z / 3, which = z % 3;
    const __nv_bfloat16* gwh = g_wh + (size_t)which * 65536;
    const __nv_bfloat16* gwl = g_wl + (size_t)which * 65536;
    const float* bias = (which == 0) ? bq : (which == 1) ? bk : bv;
    __nv_bfloat16* oh = (which == 0) ? g_qh : (which == 1) ? g_kh : g_vh;
    __nv_bfloat16* ol = (which == 0) ? g_ql : (which == 1) ? g_kl : g_vl;
    int m0 = blockIdx.y * 128, s0 = blockIdx.x * 128;
    int tid = threadIdx.x;
    size_t ob = (size_t)b * CH * SP;
    const __nv_bfloat16* xh = g_xh + ob;
    const __nv_bfloat16* xl = g_xl + ob;

    float acc[16][4];
#pragma unroll
    for (int i = 0; i < 16; i++)
#pragma unroll
        for (int j = 0; j < 4; j++) acc[i][j] = 0.0f;

    conv_gemm_body(acc, sm_u32(smem), tid, gwh, gwl, xh, xl, m0, s0);

    int w = tid >> 5, lane = tid & 31;
    int r0 = 16 * w + (lane >> 2), c2 = (lane & 3) * 2;
    float b0 = bias[m0 + r0], b1 = bias[m0 + r0 + 8];
    size_t ro0 = ob + (size_t)(m0 + r0) * SP;
    size_t ro1 = ob + (size_t)(m0 + r0 + 8) * SP;
#pragma unroll
    for (int nt = 0; nt < 8; nt++) {
        int c = s0 + nt * 16 + c2;
        uint32_t hh, ll;
        split2(acc[2 * nt][0] + b0, acc[2 * nt][1] + b0, hh, ll);
        *(uint32_t*)&oh[ro0 + c] = hh;  *(uint32_t*)&ol[ro0 + c] = ll;
        split2(acc[2 * nt][2] + b1, acc[2 * nt][3] + b1, hh, ll);
        *(uint32_t*)&oh[ro1 + c] = hh;  *(uint32_t*)&ol[ro1 + c] = ll;
        split2(acc[2 * nt + 1][0] + b0, acc[2 * nt + 1][1] + b0, hh, ll);
        *(uint32_t*)&oh[ro0 + c + 8] = hh;  *(uint32_t*)&ol[ro0 + c + 8] = ll;
        split2(acc[2 * nt + 1][2] + b1, acc[2 * nt + 1][3] + b1, hh, ll);
        *(uint32_t*)&oh[ro1 + c + 8] = hh;  *(uint32_t*)&ol[ro1 + c + 8] = ll;
    }
}

__global__ __launch_bounds__(256) void out_mma_kernel(
    const float* __restrict__ x, const float* __restrict__ bu, float* __restrict__ out)
{
    __shared__ __align__(16) char smem[2 * STG];
    int b = blockIdx.z;
    const __nv_bfloat16* gwh = g_wh + (size_t)3 * 65536;
    const __nv_bfloat16* gwl = g_wl + (size_t)3 * 65536;
    int m0 = blockIdx.y * 128, s0 = blockIdx.x * 128;
    int tid = threadIdx.x;
    size_t ob = (size_t)b * CH * SP;
    const __nv_bfloat16* ah = g_ah + ob;
    const __nv_bfloat16* al = g_al + ob;

    float acc[16][4];
#pragma unroll
    for (int i = 0; i < 16; i++)
#pragma unroll
        for (int j = 0; j < 4; j++) acc[i][j] = 0.0f;

    conv_gemm_body(acc, sm_u32(smem), tid, gwh, gwl, ah, al, m0, s0);

    int w = tid >> 5, lane = tid & 31;
    int r0 = 16 * w + (lane >> 2), c2 = (lane & 3) * 2;
    float b0 = bu[m0 + r0], b1 = bu[m0 + r0 + 8];
    size_t ro0 = ob + (size_t)(m0 + r0) * SP;
    size_t ro1 = ob + (size_t)(m0 + r0 + 8) * SP;
#pragma unroll
    for (int nt = 0; nt < 8; nt++) {
        int c = s0 + nt * 16 + c2;
        float2 x00 = *(const float2*)&x[ro0 + c];
        float2 x10 = *(const float2*)&x[ro1 + c];
        float2 x01 = *(const float2*)&x[ro0 + c + 8];
        float2 x11 = *(const float2*)&x[ro1 + c + 8];
        float2 v;
        v.x = acc[2 * nt][0] + b0 + x00.x;  v.y = acc[2 * nt][1] + b0 + x00.y;
        *(float2*)&out[ro0 + c] = v;
        v.x = acc[2 * nt][2] + b1 + x10.x;  v.y = acc[2 * nt][3] + b1 + x10.y;
        *(float2*)&out[ro1 + c] = v;
        v.x = acc[2 * nt + 1][0] + b0 + x01.x;  v.y = acc[2 * nt + 1][1] + b0 + x01.y;
        *(float2*)&out[ro0 + c + 8] = v;
        v.x = acc[2 * nt + 1][2] + b1 + x11.x;  v.y = acc[2 * nt + 1][3] + b1 + x11.y;
        *(float2*)&out[ro1 + c + 8] = v;
    }
}

// ---------------------------------------------------------------------------
// Flash attention (R10 structure + accumulator chain-breaking).
// grid (32 row-tiles of 128, 4 batches), 256 threads = 8 warps.
// ---------------------------------------------------------------------------
#define SQ 264
#define ATTN_SMEM ((2 * 128 * SQ + 4 * 32 * SQ) * 2)

__global__ __launch_bounds__(256, 1) void attn_kernel()
{
    extern __shared__ __nv_bfloat16 sm[];
    __nv_bfloat16* Qh = sm;
    __nv_bfloat16* Ql = Qh + 128 * SQ;
    __nv_bfloat16* Kh = Ql + 128 * SQ;
    __nv_bfloat16* Kl = Kh + 32 * SQ;
    __nv_bfloat16* Vh = Kl + 32 * SQ;
    __nv_bfloat16* Vl = Vh + 32 * SQ;

    int b = blockIdx.y;
    int n0 = blockIdx.x * 128;
    int tid = threadIdx.x;
    int w = tid >> 5, lane = tid & 31;

    size_t base = (size_t)b * CH * SP;
    const uint4* Qgh = (const uint4*)(g_qh + base);
    const uint4* Qgl = (const uint4*)(g_ql + base);
    const uint4* Kgh = (const uint4*)(g_kh + base);
    const uint4* Kgl = (const uint4*)(g_kl + base);
    const uint4* Vgh = (const uint4*)(g_vh + base);
    const uint4* Vgl = (const uint4*)(g_vl + base);

    int lr0 = tid >> 3, lc0 = (tid & 7) * 4;
    uint32_t sKh = sm_u32(Kh), sKl = sm_u32(Kl), sVh = sm_u32(Vh), sVl = sm_u32(Vl);

    {
        size_t g = (size_t)lr0 * 32 + lc0;
        uint32_t s = (uint32_t)(lr0 * 33 + lc0) * 16;
#pragma unroll
        for (int j = 0; j < 4; j++) {
            cpa16(sKh + s + j * 16, Kgh + g + j);
            cpa16(sKl + s + j * 16, Kgl + g + j);
        }
        cpa_commit();
    }

    for (int idx = tid; idx < 128 * 32; idx += 256) {
        int r = idx >> 5, c = idx & 31;
        ((uint4*)Qh)[r * 33 + c] = Qgh[(size_t)(n0 + r) * 32 + c];
        ((uint4*)Ql)[r * 33 + c] = Qgl[(size_t)(n0 + r) * 32 + c];
    }

    int rsel = lane & 15, csel = lane >> 4;
    uint32_t aQh = sm_u32(Qh + (w * 16 + rsel) * SQ + csel * 8);
    uint32_t aQl = aQh + 128 * SQ * 2;
    uint32_t aKh = sm_u32(Kh + rsel * SQ + csel * 8);
    uint32_t aKl = aKh + 32 * SQ * 2;
    uint32_t aVh = sm_u32(Vh + rsel * SQ + csel * 8);
    uint32_t aVl = aVh + 32 * SQ * 2;

    float o[32][4];
#pragma unroll
    for (int i = 0; i < 32; i++)
#pragma unroll
        for (int j = 0; j < 4; j++) o[i][j] = 0.0f;
    float m0r = -1e30f, m1r = -1e30f, l0r = 0.0f, l1r = 0.0f;

    for (int mt = 0; mt < 128; mt++) {
        cpa_wait_all();
        __syncthreads();

        {
            size_t g = (size_t)(mt * 32 + lr0) * 32 + lc0;
            uint32_t s = (uint32_t)(lr0 * 33 + lc0) * 16;
#pragma unroll
            for (int j = 0; j < 4; j++) {
                cpa16(sVh + s + j * 16, Vgh + g + j);
                cpa16(sVl + s + j * 16, Vgl + g + j);
            }
            cpa_commit();
        }

        // ---- S = Q K^T, split accumulators: sh = Qh*Kh, sl = Qh*Kl + Ql*Kh ----
        float sh[4][4], sl[4][4];
#pragma unroll
        for (int i = 0; i < 4; i++)
#pragma unroll
            for (int j = 0; j < 4; j++) { sh[i][j] = 0.0f; sl[i][j] = 0.0f; }

#pragma unroll
        for (int kc = 0; kc < 16; kc++) {
            uint32_t ah[4], al[4];
            ldsm4(ah, aQh + kc * 32);
            ldsm4(al, aQl + kc * 32);
#pragma unroll
            for (int np = 0; np < 2; np++) {
                uint32_t bh[4], bl[4];
                ldsm4(bh, aKh + np * (16 * SQ * 2) + kc * 32);
                ldsm4(bl, aKl + np * (16 * SQ * 2) + kc * 32);
                // interleaved across 4 independent accumulators
                mma16816(sh[2 * np],     ah, bh[0], bh[2]);
                mma16816(sl[2 * np],     ah, bl[0], bl[2]);
                mma16816(sh[2 * np + 1], ah, bh[1], bh[3]);
                mma16816(sl[2 * np + 1], ah, bl[1], bl[3]);
                mma16816(sl[2 * np],     al, bh[0], bh[2]);
                mma16816(sl[2 * np + 1], al, bh[1], bh[3]);
            }
        }

        cpa_wait_all();
        __syncthreads();

        if (mt + 1 < 128) {
            size_t g = (size_t)((mt + 1) * 32 + lr0) * 32 + lc0;
            uint32_t s2 = (uint32_t)(lr0 * 33 + lc0) * 16;
#pragma unroll
            for (int j = 0; j < 4; j++) {
                cpa16(sKh + s2 + j * 16, Kgh + g + j);
                cpa16(sKl + s2 + j * 16, Kgl + g + j);
            }
            cpa_commit();
        }

        // merge split accumulators
        float s[4][4];
#pragma unroll
        for (int i = 0; i < 4; i++)
#pragma unroll
            for (int j = 0; j < 4; j++) s[i][j] = sh[i][j] + sl[i][j];

        float mx0 = s[0][0], mx1 = s[0][2];
#pragma unroll
        for (int nt = 0; nt < 4; nt++) {
            mx0 = fmaxf(mx0, fmaxf(s[nt][0], s[nt][1]));
            mx1 = fmaxf(mx1, fmaxf(s[nt][2], s[nt][3]));
        }
        mx0 = fmaxf(mx0, __shfl_xor_sync(0xffffffffu, mx0, 1));
        mx0 = fmaxf(mx0, __shfl_xor_sync(0xffffffffu, mx0, 2));
        mx1 = fmaxf(mx1, __shfl_xor_sync(0xffffffffu, mx1, 1));
        mx1 = fmaxf(mx1, __shfl_xor_sync(0xffffffffu, mx1, 2));

        float mn0 = fmaxf(m0r, mx0), mn1 = fmaxf(m1r, mx1);
        float sc0 = __expf(m0r - mn0), sc1 = __expf(m1r - mn1);
        m0r = mn0; m1r = mn1;

        float rs0 = 0.0f, rs1 = 0.0f;
#pragma unroll
        for (int nt = 0; nt < 4; nt++) {
            s[nt][0] = __expf(s[nt][0] - mn0);
            s[nt][1] = __expf(s[nt][1] - mn0);
            s[nt][2] = __expf(s[nt][2] - mn1);
            s[nt][3] = __expf(s[nt][3] - mn1);
            rs0 += s[nt][0] + s[nt][1];
            rs1 += s[nt][2] + s[nt][3];
        }
        rs0 += __shfl_xor_sync(0xffffffffu, rs0, 1);
        rs0 += __shfl_xor_sync(0xffffffffu, rs0, 2);
        rs1 += __shfl_xor_sync(0xffffffffu, rs1, 1);
        rs1 += __shfl_xor_sync(0xffffffffu, rs1, 2);
        l0r = l0r * sc0 + rs0;
        l1r = l1r * sc1 + rs1;

#pragma unroll
        for (int nt = 0; nt < 32; nt++) {
            o[nt][0] *= sc0; o[nt][1] *= sc0;
            o[nt][2] *= sc1; o[nt][3] *= sc1;
        }

        uint32_t ph[2][4], pl[2][4];
#pragma unroll
        for (int kc = 0; kc < 2; kc++) {
            int nt0 = 2 * kc, nt1 = 2 * kc + 1;
            split2(s[nt0][0], s[nt0][1], ph[kc][0], pl[kc][0]);
            split2(s[nt0][2], s[nt0][3], ph[kc][1], pl[kc][1]);
            split2(s[nt1][0], s[nt1][1], ph[kc][2], pl[kc][2]);
            split2(s[nt1][2], s[nt1][3], ph[kc][3], pl[kc][3]);
        }

        // ---- O += P V, interleaved accumulators ----
#pragma unroll
        for (int kc = 0; kc < 2; kc++) {
#pragma unroll
            for (int ct = 0; ct < 16; ct++) {
                uint32_t vh[4], vl[4];
                ldsm4t(vh, aVh + kc * (16 * SQ * 2) + ct * 32);
                ldsm4t(vl, aVl + kc * (16 * SQ * 2) + ct * 32);
                float* oA = o[2 * ct];
                float* oB = o[2 * ct + 1];
                mma16816(oA, ph[kc], vh[0], vh[1]);
                mma16816(oB, ph[kc], vh[2], vh[3]);
                mma16816(oA, ph[kc], vl[0], vl[1]);
                mma16816(oB, ph[kc], vl[2], vl[3]);
                mma16816(oA, pl[kc], vh[0], vh[1]);
                mma16816(oB, pl[kc], vh[2], vh[3]);
            }
        }
    }

    // epilogue: normalize, store bf16 hi/lo
    float inv0 = 1.0f / l0r, inv1 = 1.0f / l1r;
    int r0 = n0 + w * 16 + (lane >> 2);
    int r1 = r0 + 8;
    int cb = (lane & 3) * 2;
#pragma unroll
    for (int nt = 0; nt < 32; nt++) {
        int c = nt * 8 + cb;
        uint32_t hh, ll;
        split2(o[nt][0] * inv0, o[nt][1] * inv0, hh, ll);
        *(uint32_t*)&g_ah[base + (size_t)r0 * 256 + c] = hh;
        *(uint32_t*)&g_al[base + (size_t)r0 * 256 + c] = ll;
        split2(o[nt][2] * inv1, o[nt][3] * inv1, hh, ll);
        *(uint32_t*)&g_ah[base + (size_t)r1 * 256 + c] = hh;
        *(uint32_t*)&g_al[base + (size_t)r1 * 256 + c] = ll;
    }
}

// ---------------------------------------------------------------------------
extern "C" void kernel_launch(void* const* d_in, const int* in_sizes, int n_in,
                              void* d_out, int out_size)
{
    (void)in_sizes; (void)n_in; (void)out_size;
    const float* x  = (const float*)d_in[0];
    const float* Wq = (const float*)d_in[1];
    const float* bq = (const float*)d_in[2];
    const float* Wk = (const float*)d_in[3];
    const float* bk = (const float*)d_in[4];
    const float* Wv = (const float*)d_in[5];
    const float* bv = (const float*)d_in[6];
    const float* Wu = (const float*)d_in[7];
    const float* bu = (const float*)d_in[8];
    float* out = (float*)d_out;

    cudaFuncSetAttribute(attn_kernel, cudaFuncAttributeMaxDynamicSharedMemorySize, ATTN_SMEM);

    splitx_kernel<<<4096, 256>>>(x);
    splitw_kernel<<<256, 256>>>(Wq, Wk, Wv, Wu);
    qkv_mma_kernel<<<dim3(32, 2, 12), 256>>>(bq, bk, bv);
    attn_kernel<<<dim3(32, 4), 256, ATTN_SMEM>>>();
    out_mma_kernel<<<dim3(32, 2, 4), 256>>>(x, bu, out);
}

// round 14
// speedup vs baseline: 1.4705x; 1.0982x over previous
#include <cuda_runtime.h>
#include <cuda_bf16.h>
#include <cuda_fp16.h>
#include <cstdint>

#define BATCH 4
#define CH    256
#define SP    4096
#define DH    256

__device__ __align__(16) __nv_bfloat16 g_xh[BATCH * CH * SP];
__device__ __align__(16) __nv_bfloat16 g_xl[BATCH * CH * SP];
__device__ __align__(16) __nv_bfloat16 g_wh[4 * 65536];
__device__ __align__(16) __nv_bfloat16 g_wl[4 * 65536];
__device__ __align__(16) __nv_bfloat16 g_qh[BATCH * CH * SP];
__device__ __align__(16) __nv_bfloat16 g_ql[BATCH * CH * SP];
__device__ __align__(16) __nv_bfloat16 g_kh[BATCH * CH * SP];
__device__ __align__(16) __nv_bfloat16 g_kl[BATCH * CH * SP];
// V is stored as fp16 hi/lo (written packed by qkv_mma epilogue)
__device__ __align__(16) __half g_vh[BATCH * CH * SP];
__device__ __align__(16) __half g_vl[BATCH * CH * SP];
__device__ __align__(16) __nv_bfloat16 g_ah[BATCH * CH * SP];
__device__ __align__(16) __nv_bfloat16 g_al[BATCH * CH * SP];

// ---------------- helpers ----------------
__device__ __forceinline__ uint32_t pk(float x0, float x1) {
    uint32_t r;
    asm("cvt.rn.bf16x2.f32 %0, %1, %2;" : "=r"(r) : "f"(x1), "f"(x0));
    return r;
}
__device__ __forceinline__ void split2(float x0, float x1, uint32_t& hi, uint32_t& lo) {
    float h0 = __bfloat162float(__float2bfloat16(x0));
    float h1 = __bfloat162float(__float2bfloat16(x1));
    hi = pk(x0, x1);
    lo = pk(x0 - h0, x1 - h1);
}
__device__ __forceinline__ uint32_t pkh(float x0, float x1) {
    uint32_t r;
    asm("cvt.rn.f16x2.f32 %0, %1, %2;" : "=r"(r) : "f"(x1), "f"(x0));
    return r;
}
__device__ __forceinline__ void split2h(float x0, float x1, uint32_t& hi, uint32_t& lo) {
    float h0 = __half2float(__float2half_rn(x0));
    float h1 = __half2float(__float2half_rn(x1));
    hi = pkh(x0, x1);
    lo = pkh(x0 - h0, x1 - h1);
}
__device__ __forceinline__ void ldsm4(uint32_t* r, uint32_t a) {
    asm volatile("ldmatrix.sync.aligned.m8n8.x4.shared.b16 {%0,%1,%2,%3}, [%4];"
                 : "=r"(r[0]), "=r"(r[1]), "=r"(r[2]), "=r"(r[3]) : "r"(a));
}
__device__ __forceinline__ void ldsm4t(uint32_t* r, uint32_t a) {
    asm volatile("ldmatrix.sync.aligned.m8n8.x4.trans.shared.b16 {%0,%1,%2,%3}, [%4];"
                 : "=r"(r[0]), "=r"(r[1]), "=r"(r[2]), "=r"(r[3]) : "r"(a));
}
__device__ __forceinline__ void mma16816(float* d, const uint32_t* a, uint32_t b0, uint32_t b1) {
    asm volatile("mma.sync.aligned.m16n8k16.row.col.f32.bf16.bf16.f32 "
                 "{%0,%1,%2,%3}, {%4,%5,%6,%7}, {%8,%9}, {%0,%1,%2,%3};"
                 : "+f"(d[0]), "+f"(d[1]), "+f"(d[2]), "+f"(d[3])
                 : "r"(a[0]), "r"(a[1]), "r"(a[2]), "r"(a[3]), "r"(b0), "r"(b1));
}
__device__ __forceinline__ void mma16816h(float* d, const uint32_t* a, uint32_t b0, uint32_t b1) {
    asm volatile("mma.sync.aligned.m16n8k16.row.col.f32.f16.f16.f32 "
                 "{%0,%1,%2,%3}, {%4,%5,%6,%7}, {%8,%9}, {%0,%1,%2,%3};"
                 : "+f"(d[0]), "+f"(d[1]), "+f"(d[2]), "+f"(d[3])
                 : "r"(a[0]), "r"(a[1]), "r"(a[2]), "r"(a[3]), "r"(b0), "r"(b1));
}
__device__ __forceinline__ uint32_t sm_u32(const void* p) {
    return (uint32_t)__cvta_generic_to_shared(p);
}
__device__ __forceinline__ void cpa16(uint32_t dst, const void* src) {
    asm volatile("cp.async.cg.shared.global [%0], [%1], 16;" :: "r"(dst), "l"(src));
}
__device__ __forceinline__ void cpa_commit() { asm volatile("cp.async.commit_group;"); }
__device__ __forceinline__ void cpa_wait_all() { asm volatile("cp.async.wait_group 0;"); }

// ---------------------------------------------------------------------------
// Split kernels: fp32 -> bf16 hi/lo
// ---------------------------------------------------------------------------
__global__ __launch_bounds__(256) void splitx_kernel(const float* __restrict__ x)
{
    size_t i = ((size_t)blockIdx.x * 256 + threadIdx.x) * 4;
    float4 v = *(const float4*)(x + i);
    uint32_t h0, l0, h1, l1;
    split2(v.x, v.y, h0, l0);
    split2(v.z, v.w, h1, l1);
    uint2 hw, lw;
    hw.x = h0; hw.y = h1; lw.x = l0; lw.y = l1;
    *(uint2*)&g_xh[i] = hw;
    *(uint2*)&g_xl[i] = lw;
}

__global__ __launch_bounds__(256) void splitw_kernel(
    const float* __restrict__ Wq, const float* __restrict__ Wk,
    const float* __restrict__ Wv, const float* __restrict__ Wu)
{
    size_t i = ((size_t)blockIdx.x * 256 + threadIdx.x) * 4;
    int which = (int)(i >> 16);
    const float* W = (which == 0) ? Wq : (which == 1) ? Wk : (which == 2) ? Wv : Wu;
    float4 v = *(const float4*)(W + (i & 65535));
    uint32_t h0, l0, h1, l1;
    split2(v.x, v.y, h0, l0);
    split2(v.z, v.w, h1, l1);
    uint2 hw, lw;
    hw.x = h0; hw.y = h1; lw.x = l0; lw.y = l1;
    *(uint2*)&g_wh[i] = hw;
    *(uint2*)&g_wl[i] = lw;
}

// ---------------------------------------------------------------------------
// Conv GEMM on tensor cores (bf16 hi/lo, 3-term). CTA: 128(out-ch) x 128(sp).
// ---------------------------------------------------------------------------
#define STG 21504
#define WL_OFF 6144
#define XH_OFF 12288
#define XL_OFF 16640

__device__ __forceinline__ void conv_issue(
    uint32_t sb, int tid, int kc,
    const __nv_bfloat16* gwh, const __nv_bfloat16* gwl,
    const __nv_bfloat16* xh, const __nv_bfloat16* xl,
    int m0, int s0)
{
    int mm = tid & 127, g = tid >> 7;
    const __nv_bfloat16* swh = gwh + (size_t)(m0 + mm) * 256 + kc * 16 + g * 8;
    const __nv_bfloat16* swl = gwl + (size_t)(m0 + mm) * 256 + kc * 16 + g * 8;
    cpa16(sb + mm * 48 + g * 16, swh);
    cpa16(sb + WL_OFF + mm * 48 + g * 16, swl);
    int kk = tid >> 4, sg = (tid & 15) * 8;
    const __nv_bfloat16* sxh = xh + (size_t)(kc * 16 + kk) * SP + s0 + sg;
    const __nv_bfloat16* sxl = xl + (size_t)(kc * 16 + kk) * SP + s0 + sg;
    cpa16(sb + XH_OFF + kk * 272 + sg * 2, sxh);
    cpa16(sb + XL_OFF + kk * 272 + sg * 2, sxl);
}

__device__ __forceinline__ void conv_gemm_body(
    float acc[16][4], uint32_t smb, int tid,
    const __nv_bfloat16* gwh, const __nv_bfloat16* gwl,
    const __nv_bfloat16* xh, const __nv_bfloat16* xl,
    int m0, int s0)
{
    int w = tid >> 5, lane = tid & 31;
    int rsel = lane & 15, csel = lane >> 4;

    conv_issue(smb, tid, 0, gwh, gwl, xh, xl, m0, s0);
    cpa_commit();

    for (int kc = 0; kc < 16; kc++) {
        cpa_wait_all();
        __syncthreads();
        if (kc < 15) {
            conv_issue(smb + ((kc + 1) & 1) * STG, tid, kc + 1, gwh, gwl, xh, xl, m0, s0);
            cpa_commit();
        }
        uint32_t base = smb + (kc & 1) * STG;
        uint32_t aW  = base + (16 * w + rsel) * 48 + csel * 16;
        uint32_t aWl = aW + WL_OFF;
        uint32_t aX  = base + XH_OFF + rsel * 272 + csel * 16;
        uint32_t aXl = aX + (XL_OFF - XH_OFF);

        uint32_t awh[4], awl[4];
        ldsm4(awh, aW);
        ldsm4(awl, aWl);
#pragma unroll
        for (int nt = 0; nt < 8; nt++) {
            uint32_t bxh[4], bxl[4];
            ldsm4t(bxh, aX + nt * 32);
            ldsm4t(bxl, aXl + nt * 32);
            float* oA = acc[2 * nt];
            float* oB = acc[2 * nt + 1];
            mma16816(oA, awh, bxh[0], bxh[1]);
            mma16816(oB, awh, bxh[2], bxh[3]);
            mma16816(oA, awh, bxl[0], bxl[1]);
            mma16816(oB, awh, bxl[2], bxl[3]);
            mma16816(oA, awl, bxh[0], bxh[1]);
            mma16816(oB, awl, bxh[2], bxh[3]);
        }
    }
}

__global__ __launch_bounds__(256) void qkv_mma_kernel(
    const float* __restrict__ bq, const float* __restrict__ bk, const float* __restrict__ bv)
{
    __shared__ __align__(16) char smem[2 * STG];
    int z = blockIdx.z, b = z / 3, which = z % 3;
    const __nv_bfloat16* gwh = g_wh + (size_t)which * 65536;
    const __nv_bfloat16* gwl = g_wl + (size_t)which * 65536;
    const float* bias = (which == 0) ? bq : (which == 1) ? bk : bv;
    // V outputs are fp16 hi/lo (stored packed); Q/K are bf16 hi/lo
    void* ohv = (which == 0) ? (void*)g_qh : (which == 1) ? (void*)g_kh : (void*)g_vh;
    void* olv = (which == 0) ? (void*)g_ql : (which == 1) ? (void*)g_kl : (void*)g_vl;
    uint16_t* oh = (uint16_t*)ohv;
    uint16_t* ol = (uint16_t*)olv;
    int m0 = blockIdx.y * 128, s0 = blockIdx.x * 128;
    int tid = threadIdx.x;
    size_t ob = (size_t)b * CH * SP;
    const __nv_bfloat16* xh = g_xh + ob;
    const __nv_bfloat16* xl = g_xl + ob;

    float acc[16][4];
#pragma unroll
    for (int i = 0; i < 16; i++)
#pragma unroll
        for (int j = 0; j < 4; j++) acc[i][j] = 0.0f;

    conv_gemm_body(acc, sm_u32(smem), tid, gwh, gwl, xh, xl, m0, s0);

    int w = tid >> 5, lane = tid & 31;
    int r0 = 16 * w + (lane >> 2), c2 = (lane & 3) * 2;
    float b0 = bias[m0 + r0], b1 = bias[m0 + r0 + 8];
    size_t ro0 = ob + (size_t)(m0 + r0) * SP;
    size_t ro1 = ob + (size_t)(m0 + r0 + 8) * SP;
    bool f16out = (which == 2);
#pragma unroll
    for (int nt = 0; nt < 8; nt++) {
        int c = s0 + nt * 16 + c2;
        uint32_t hh, ll;
        float v0 = acc[2 * nt][0] + b0, v1 = acc[2 * nt][1] + b0;
        if (f16out) split2h(v0, v1, hh, ll); else split2(v0, v1, hh, ll);
        *(uint32_t*)&oh[ro0 + c] = hh;  *(uint32_t*)&ol[ro0 + c] = ll;
        v0 = acc[2 * nt][2] + b1; v1 = acc[2 * nt][3] + b1;
        if (f16out) split2h(v0, v1, hh, ll); else split2(v0, v1, hh, ll);
        *(uint32_t*)&oh[ro1 + c] = hh;  *(uint32_t*)&ol[ro1 + c] = ll;
        v0 = acc[2 * nt + 1][0] + b0; v1 = acc[2 * nt + 1][1] + b0;
        if (f16out) split2h(v0, v1, hh, ll); else split2(v0, v1, hh, ll);
        *(uint32_t*)&oh[ro0 + c + 8] = hh;  *(uint32_t*)&ol[ro0 + c + 8] = ll;
        v0 = acc[2 * nt + 1][2] + b1; v1 = acc[2 * nt + 1][3] + b1;
        if (f16out) split2h(v0, v1, hh, ll); else split2(v0, v1, hh, ll);
        *(uint32_t*)&oh[ro1 + c + 8] = hh;  *(uint32_t*)&ol[ro1 + c + 8] = ll;
    }
}

__global__ __launch_bounds__(256) void out_mma_kernel(
    const float* __restrict__ x, const float* __restrict__ bu, float* __restrict__ out)
{
    __shared__ __align__(16) char smem[2 * STG];
    int b = blockIdx.z;
    const __nv_bfloat16* gwh = g_wh + (size_t)3 * 65536;
    const __nv_bfloat16* gwl = g_wl + (size_t)3 * 65536;
    int m0 = blockIdx.y * 128, s0 = blockIdx.x * 128;
    int tid = threadIdx.x;
    size_t ob = (size_t)b * CH * SP;
    const __nv_bfloat16* ah = g_ah + ob;
    const __nv_bfloat16* al = g_al + ob;

    float acc[16][4];
#pragma unroll
    for (int i = 0; i < 16; i++)
#pragma unroll
        for (int j = 0; j < 4; j++) acc[i][j] = 0.0f;

    conv_gemm_body(acc, sm_u32(smem), tid, gwh, gwl, ah, al, m0, s0);

    int w = tid >> 5, lane = tid & 31;
    int r0 = 16 * w + (lane >> 2), c2 = (lane & 3) * 2;
    float b0 = bu[m0 + r0], b1 = bu[m0 + r0 + 8];
    size_t ro0 = ob + (size_t)(m0 + r0) * SP;
    size_t ro1 = ob + (size_t)(m0 + r0 + 8) * SP;
#pragma unroll
    for (int nt = 0; nt < 8; nt++) {
        int c = s0 + nt * 16 + c2;
        float2 x00 = *(const float2*)&x[ro0 + c];
        float2 x10 = *(const float2*)&x[ro1 + c];
        float2 x01 = *(const float2*)&x[ro0 + c + 8];
        float2 x11 = *(const float2*)&x[ro1 + c + 8];
        float2 v;
        v.x = acc[2 * nt][0] + b0 + x00.x;  v.y = acc[2 * nt][1] + b0 + x00.y;
        *(float2*)&out[ro0 + c] = v;
        v.x = acc[2 * nt][2] + b1 + x10.x;  v.y = acc[2 * nt][3] + b1 + x10.y;
        *(float2*)&out[ro1 + c] = v;
        v.x = acc[2 * nt + 1][0] + b0 + x01.x;  v.y = acc[2 * nt + 1][1] + b0 + x01.y;
        *(float2*)&out[ro0 + c + 8] = v;
        v.x = acc[2 * nt + 1][2] + b1 + x11.x;  v.y = acc[2 * nt + 1][3] + b1 + x11.y;
        *(float2*)&out[ro1 + c + 8] = v;
    }
}

// ---------------------------------------------------------------------------
// Flash attention. S: bf16 3-term (chain-broken). PV: fp16 2-term
// (O += Ph*Vh + Ph*Vl; Pl dropped, err ~2^-12).
// grid (32 row-tiles of 128, 4 batches), 256 threads = 8 warps.
// ---------------------------------------------------------------------------
#define SQ 264
#define ATTN_SMEM ((2 * 128 * SQ + 4 * 32 * SQ) * 2)

__global__ __launch_bounds__(256, 1) void attn_kernel()
{
    extern __shared__ __nv_bfloat16 sm[];
    __nv_bfloat16* Qh = sm;
    __nv_bfloat16* Ql = Qh + 128 * SQ;
    __nv_bfloat16* Kh = Ql + 128 * SQ;
    __nv_bfloat16* Kl = Kh + 32 * SQ;
    __nv_bfloat16* Vh = Kl + 32 * SQ;   // holds fp16 bits
    __nv_bfloat16* Vl = Vh + 32 * SQ;   // holds fp16 bits

    int b = blockIdx.y;
    int n0 = blockIdx.x * 128;
    int tid = threadIdx.x;
    int w = tid >> 5, lane = tid & 31;

    size_t base = (size_t)b * CH * SP;
    const uint4* Qgh = (const uint4*)(g_qh + base);
    const uint4* Qgl = (const uint4*)(g_ql + base);
    const uint4* Kgh = (const uint4*)(g_kh + base);
    const uint4* Kgl = (const uint4*)(g_kl + base);
    const uint4* Vgh = (const uint4*)(g_vh + base);
    const uint4* Vgl = (const uint4*)(g_vl + base);

    int lr0 = tid >> 3, lc0 = (tid & 7) * 4;
    uint32_t sKh = sm_u32(Kh), sKl = sm_u32(Kl), sVh = sm_u32(Vh), sVl = sm_u32(Vl);

    {
        size_t g = (size_t)lr0 * 32 + lc0;
        uint32_t s = (uint32_t)(lr0 * 33 + lc0) * 16;
#pragma unroll
        for (int j = 0; j < 4; j++) {
            cpa16(sKh + s + j * 16, Kgh + g + j);
            cpa16(sKl + s + j * 16, Kgl + g + j);
        }
        cpa_commit();
    }

    for (int idx = tid; idx < 128 * 32; idx += 256) {
        int r = idx >> 5, c = idx & 31;
        ((uint4*)Qh)[r * 33 + c] = Qgh[(size_t)(n0 + r) * 32 + c];
        ((uint4*)Ql)[r * 33 + c] = Qgl[(size_t)(n0 + r) * 32 + c];
    }

    int rsel = lane & 15, csel = lane >> 4;
    uint32_t aQh = sm_u32(Qh + (w * 16 + rsel) * SQ + csel * 8);
    uint32_t aQl = aQh + 128 * SQ * 2;
    uint32_t aKh = sm_u32(Kh + rsel * SQ + csel * 8);
    uint32_t aKl = aKh + 32 * SQ * 2;
    uint32_t aVh = sm_u32(Vh + rsel * SQ + csel * 8);
    uint32_t aVl = aVh + 32 * SQ * 2;

    float o[32][4];
#pragma unroll
    for (int i = 0; i < 32; i++)
#pragma unroll
        for (int j = 0; j < 4; j++) o[i][j] = 0.0f;
    float m0r = -1e30f, m1r = -1e30f, l0r = 0.0f, l1r = 0.0f;

    for (int mt = 0; mt < 128; mt++) {
        cpa_wait_all();
        __syncthreads();

        {
            size_t g = (size_t)(mt * 32 + lr0) * 32 + lc0;
            uint32_t s = (uint32_t)(lr0 * 33 + lc0) * 16;
#pragma unroll
            for (int j = 0; j < 4; j++) {
                cpa16(sVh + s + j * 16, Vgh + g + j);
                cpa16(sVl + s + j * 16, Vgl + g + j);
            }
            cpa_commit();
        }

        // ---- S = Q K^T, split accumulators (chain-broken, R13) ----
        float sh[4][4], sl[4][4];
#pragma unroll
        for (int i = 0; i < 4; i++)
#pragma unroll
            for (int j = 0; j < 4; j++) { sh[i][j] = 0.0f; sl[i][j] = 0.0f; }

#pragma unroll
        for (int kc = 0; kc < 16; kc++) {
            uint32_t ah[4], al[4];
            ldsm4(ah, aQh + kc * 32);
            ldsm4(al, aQl + kc * 32);
#pragma unroll
            for (int np = 0; np < 2; np++) {
                uint32_t bh[4], bl[4];
                ldsm4(bh, aKh + np * (16 * SQ * 2) + kc * 32);
                ldsm4(bl, aKl + np * (16 * SQ * 2) + kc * 32);
                mma16816(sh[2 * np],     ah, bh[0], bh[2]);
                mma16816(sl[2 * np],     ah, bl[0], bl[2]);
                mma16816(sh[2 * np + 1], ah, bh[1], bh[3]);
                mma16816(sl[2 * np + 1], ah, bl[1], bl[3]);
                mma16816(sl[2 * np],     al, bh[0], bh[2]);
                mma16816(sl[2 * np + 1], al, bh[1], bh[3]);
            }
        }

        cpa_wait_all();
        __syncthreads();

        if (mt + 1 < 128) {
            size_t g = (size_t)((mt + 1) * 32 + lr0) * 32 + lc0;
            uint32_t s2 = (uint32_t)(lr0 * 33 + lc0) * 16;
#pragma unroll
            for (int j = 0; j < 4; j++) {
                cpa16(sKh + s2 + j * 16, Kgh + g + j);
                cpa16(sKl + s2 + j * 16, Kgl + g + j);
            }
            cpa_commit();
        }

        float s[4][4];
#pragma unroll
        for (int i = 0; i < 4; i++)
#pragma unroll
            for (int j = 0; j < 4; j++) s[i][j] = sh[i][j] + sl[i][j];

        float mx0 = s[0][0], mx1 = s[0][2];
#pragma unroll
        for (int nt = 0; nt < 4; nt++) {
            mx0 = fmaxf(mx0, fmaxf(s[nt][0], s[nt][1]));
            mx1 = fmaxf(mx1, fmaxf(s[nt][2], s[nt][3]));
        }
        mx0 = fmaxf(mx0, __shfl_xor_sync(0xffffffffu, mx0, 1));
        mx0 = fmaxf(mx0, __shfl_xor_sync(0xffffffffu, mx0, 2));
        mx1 = fmaxf(mx1, __shfl_xor_sync(0xffffffffu, mx1, 1));
        mx1 = fmaxf(mx1, __shfl_xor_sync(0xffffffffu, mx1, 2));

        float mn0 = fmaxf(m0r, mx0), mn1 = fmaxf(m1r, mx1);
        float sc0 = __expf(m0r - mn0), sc1 = __expf(m1r - mn1);
        m0r = mn0; m1r = mn1;

        float rs0 = 0.0f, rs1 = 0.0f;
#pragma unroll
        for (int nt = 0; nt < 4; nt++) {
            s[nt][0] = __expf(s[nt][0] - mn0);
            s[nt][1] = __expf(s[nt][1] - mn0);
            s[nt][2] = __expf(s[nt][2] - mn1);
            s[nt][3] = __expf(s[nt][3] - mn1);
            rs0 += s[nt][0] + s[nt][1];
            rs1 += s[nt][2] + s[nt][3];
        }
        rs0 += __shfl_xor_sync(0xffffffffu, rs0, 1);
        rs0 += __shfl_xor_sync(0xffffffffu, rs0, 2);
        rs1 += __shfl_xor_sync(0xffffffffu, rs1, 1);
        rs1 += __shfl_xor_sync(0xffffffffu, rs1, 2);
        l0r = l0r * sc0 + rs0;
        l1r = l1r * sc1 + rs1;

#pragma unroll
        for (int nt = 0; nt < 32; nt++) {
            o[nt][0] *= sc0; o[nt][1] *= sc0;
            o[nt][2] *= sc1; o[nt][3] *= sc1;
        }

        // P -> fp16 A-fragments (hi only; Pl dropped)
        uint32_t ph[2][4];
#pragma unroll
        for (int kc = 0; kc < 2; kc++) {
            int nt0 = 2 * kc, nt1 = 2 * kc + 1;
            ph[kc][0] = pkh(s[nt0][0], s[nt0][1]);
            ph[kc][1] = pkh(s[nt0][2], s[nt0][3]);
            ph[kc][2] = pkh(s[nt1][0], s[nt1][1]);
            ph[kc][3] = pkh(s[nt1][2], s[nt1][3]);
        }

        // ---- O += Ph Vh + Ph Vl (fp16, 2-term, interleaved accumulators) ----
#pragma unroll
        for (int kc = 0; kc < 2; kc++) {
#pragma unroll
            for (int ct = 0; ct < 16; ct++) {
                uint32_t vh[4], vl[4];
                ldsm4t(vh, aVh + kc * (16 * SQ * 2) + ct * 32);
                ldsm4t(vl, aVl + kc * (16 * SQ * 2) + ct * 32);
                float* oA = o[2 * ct];
                float* oB = o[2 * ct + 1];
                mma16816h(oA, ph[kc], vh[0], vh[1]);
                mma16816h(oB, ph[kc], vh[2], vh[3]);
                mma16816h(oA, ph[kc], vl[0], vl[1]);
                mma16816h(oB, ph[kc], vl[2], vl[3]);
            }
        }
    }

    // epilogue: normalize, store bf16 hi/lo
    float inv0 = 1.0f / l0r, inv1 = 1.0f / l1r;
    int r0 = n0 + w * 16 + (lane >> 2);
    int r1 = r0 + 8;
    int cb = (lane & 3) * 2;
#pragma unroll
    for (int nt = 0; nt < 32; nt++) {
        int c = nt * 8 + cb;
        uint32_t hh, ll;
        split2(o[nt][0] * inv0, o[nt][1] * inv0, hh, ll);
        *(uint32_t*)&g_ah[base + (size_t)r0 * 256 + c] = hh;
        *(uint32_t*)&g_al[base + (size_t)r0 * 256 + c] = ll;
        split2(o[nt][2] * inv1, o[nt][3] * inv1, hh, ll);
        *(uint32_t*)&g_ah[base + (size_t)r1 * 256 + c] = hh;
        *(uint32_t*)&g_al[base + (size_t)r1 * 256 + c] = ll;
    }
}

// ---------------------------------------------------------------------------
extern "C" void kernel_launch(void* const* d_in, const int* in_sizes, int n_in,
                              void* d_out, int out_size)
{
    (void)in_sizes; (void)n_in; (void)out_size;
    const float* x  = (const float*)d_in[0];
    const float* Wq = (const float*)d_in[1];
    const float* bq = (const float*)d_in[2];
    const float* Wk = (const float*)d_in[3];
    const float* bk = (const float*)d_in[4];
    const float* Wv = (const float*)d_in[5];
    const float* bv = (const float*)d_in[6];
    const float* Wu = (const float*)d_in[7];
    const float* bu = (const float*)d_in[8];
    float* out = (float*)d_out;

    cudaFuncSetAttribute(attn_kernel, cudaFuncAttributeMaxDynamicSharedMemorySize, ATTN_SMEM);

    splitx_kernel<<<4096, 256>>>(x);
    splitw_kernel<<<256, 256>>>(Wq, Wk, Wv, Wu);
    qkv_mma_kernel<<<dim3(32, 2, 12), 256>>>(bq, bk, bv);
    attn_kernel<<<dim3(32, 4), 256, ATTN_SMEM>>>();
    out_mma_kernel<<<dim3(32, 2, 4), 256>>>(x, bu, out);
}

// round 15
// speedup vs baseline: 1.6805x; 1.1429x over previous
#include <cuda_runtime.h>
#include <cuda_bf16.h>
#include <cuda_fp16.h>
#include <cstdint>

#define BATCH 4
#define CH    256
#define SP    4096
#define DH    256

__device__ __align__(16) __nv_bfloat16 g_xh[BATCH * CH * SP];
__device__ __align__(16) __nv_bfloat16 g_xl[BATCH * CH * SP];
__device__ __align__(16) __nv_bfloat16 g_wh[4 * 65536];
__device__ __align__(16) __nv_bfloat16 g_wl[4 * 65536];
__device__ __align__(16) __nv_bfloat16 g_qh[BATCH * CH * SP];
__device__ __align__(16) __nv_bfloat16 g_ql[BATCH * CH * SP];
__device__ __align__(16) __nv_bfloat16 g_kh[BATCH * CH * SP];
__device__ __align__(16) __nv_bfloat16 g_kl[BATCH * CH * SP];
__device__ __align__(16) __half g_vh[BATCH * CH * SP];   // V fp16 (single precision level)
__device__ __align__(16) __half g_vl[BATCH * CH * SP];   // written, not read (kept for epilogue symmetry)
__device__ __align__(16) __nv_bfloat16 g_ah[BATCH * CH * SP];
__device__ __align__(16) __nv_bfloat16 g_al[BATCH * CH * SP];

// ---------------- helpers ----------------
__device__ __forceinline__ uint32_t pk(float x0, float x1) {
    uint32_t r;
    asm("cvt.rn.bf16x2.f32 %0, %1, %2;" : "=r"(r) : "f"(x1), "f"(x0));
    return r;
}
__device__ __forceinline__ void split2(float x0, float x1, uint32_t& hi, uint32_t& lo) {
    float h0 = __bfloat162float(__float2bfloat16(x0));
    float h1 = __bfloat162float(__float2bfloat16(x1));
    hi = pk(x0, x1);
    lo = pk(x0 - h0, x1 - h1);
}
__device__ __forceinline__ uint32_t pkh(float x0, float x1) {
    uint32_t r;
    asm("cvt.rn.f16x2.f32 %0, %1, %2;" : "=r"(r) : "f"(x1), "f"(x0));
    return r;
}
__device__ __forceinline__ void split2h(float x0, float x1, uint32_t& hi, uint32_t& lo) {
    float h0 = __half2float(__float2half_rn(x0));
    float h1 = __half2float(__float2half_rn(x1));
    hi = pkh(x0, x1);
    lo = pkh(x0 - h0, x1 - h1);
}
__device__ __forceinline__ void ldsm4(uint32_t* r, uint32_t a) {
    asm volatile("ldmatrix.sync.aligned.m8n8.x4.shared.b16 {%0,%1,%2,%3}, [%4];"
                 : "=r"(r[0]), "=r"(r[1]), "=r"(r[2]), "=r"(r[3]) : "r"(a));
}
__device__ __forceinline__ void ldsm4t(uint32_t* r, uint32_t a) {
    asm volatile("ldmatrix.sync.aligned.m8n8.x4.trans.shared.b16 {%0,%1,%2,%3}, [%4];"
                 : "=r"(r[0]), "=r"(r[1]), "=r"(r[2]), "=r"(r[3]) : "r"(a));
}
__device__ __forceinline__ void mma16816(float* d, const uint32_t* a, uint32_t b0, uint32_t b1) {
    asm volatile("mma.sync.aligned.m16n8k16.row.col.f32.bf16.bf16.f32 "
                 "{%0,%1,%2,%3}, {%4,%5,%6,%7}, {%8,%9}, {%0,%1,%2,%3};"
                 : "+f"(d[0]), "+f"(d[1]), "+f"(d[2]), "+f"(d[3])
                 : "r"(a[0]), "r"(a[1]), "r"(a[2]), "r"(a[3]), "r"(b0), "r"(b1));
}
__device__ __forceinline__ void mma16816h(float* d, const uint32_t* a, uint32_t b0, uint32_t b1) {
    asm volatile("mma.sync.aligned.m16n8k16.row.col.f32.f16.f16.f32 "
                 "{%0,%1,%2,%3}, {%4,%5,%6,%7}, {%8,%9}, {%0,%1,%2,%3};"
                 : "+f"(d[0]), "+f"(d[1]), "+f"(d[2]), "+f"(d[3])
                 : "r"(a[0]), "r"(a[1]), "r"(a[2]), "r"(a[3]), "r"(b0), "r"(b1));
}
__device__ __forceinline__ uint32_t sm_u32(const void* p) {
    return (uint32_t)__cvta_generic_to_shared(p);
}
__device__ __forceinline__ void cpa16(uint32_t dst, const void* src) {
    asm volatile("cp.async.cg.shared.global [%0], [%1], 16;" :: "r"(dst), "l"(src));
}
__device__ __forceinline__ void cpa_commit() { asm volatile("cp.async.commit_group;"); }
__device__ __forceinline__ void cpa_wait_all() { asm volatile("cp.async.wait_group 0;"); }

// ---------------------------------------------------------------------------
// Split kernels: fp32 -> bf16 hi/lo
// ---------------------------------------------------------------------------
__global__ __launch_bounds__(256) void splitx_kernel(const float* __restrict__ x)
{
    size_t i = ((size_t)blockIdx.x * 256 + threadIdx.x) * 4;
    float4 v = *(const float4*)(x + i);
    uint32_t h0, l0, h1, l1;
    split2(v.x, v.y, h0, l0);
    split2(v.z, v.w, h1, l1);
    uint2 hw, lw;
    hw.x = h0; hw.y = h1; lw.x = l0; lw.y = l1;
    *(uint2*)&g_xh[i] = hw;
    *(uint2*)&g_xl[i] = lw;
}

__global__ __launch_bounds__(256) void splitw_kernel(
    const float* __restrict__ Wq, const float* __restrict__ Wk,
    const float* __restrict__ Wv, const float* __restrict__ Wu)
{
    size_t i = ((size_t)blockIdx.x * 256 + threadIdx.x) * 4;
    int which = (int)(i >> 16);
    const float* W = (which == 0) ? Wq : (which == 1) ? Wk : (which == 2) ? Wv : Wu;
    float4 v = *(const float4*)(W + (i & 65535));
    uint32_t h0, l0, h1, l1;
    split2(v.x, v.y, h0, l0);
    split2(v.z, v.w, h1, l1);
    uint2 hw, lw;
    hw.x = h0; hw.y = h1; lw.x = l0; lw.y = l1;
    *(uint2*)&g_wh[i] = hw;
    *(uint2*)&g_wl[i] = lw;
}

// ---------------------------------------------------------------------------
// Conv GEMM on tensor cores (bf16 hi/lo, 3-term). CTA: 128(out-ch) x 128(sp).
// ---------------------------------------------------------------------------
#define STG 21504
#define WL_OFF 6144
#define XH_OFF 12288
#define XL_OFF 16640

__device__ __forceinline__ void conv_issue(
    uint32_t sb, int tid, int kc,
    const __nv_bfloat16* gwh, const __nv_bfloat16* gwl,
    const __nv_bfloat16* xh, const __nv_bfloat16* xl,
    int m0, int s0)
{
    int mm = tid & 127, g = tid >> 7;
    const __nv_bfloat16* swh = gwh + (size_t)(m0 + mm) * 256 + kc * 16 + g * 8;
    const __nv_bfloat16* swl = gwl + (size_t)(m0 + mm) * 256 + kc * 16 + g * 8;
    cpa16(sb + mm * 48 + g * 16, swh);
    cpa16(sb + WL_OFF + mm * 48 + g * 16, swl);
    int kk = tid >> 4, sg = (tid & 15) * 8;
    const __nv_bfloat16* sxh = xh + (size_t)(kc * 16 + kk) * SP + s0 + sg;
    const __nv_bfloat16* sxl = xl + (size_t)(kc * 16 + kk) * SP + s0 + sg;
    cpa16(sb + XH_OFF + kk * 272 + sg * 2, sxh);
    cpa16(sb + XL_OFF + kk * 272 + sg * 2, sxl);
}

__device__ __forceinline__ void conv_gemm_body(
    float acc[16][4], uint32_t smb, int tid,
    const __nv_bfloat16* gwh, const __nv_bfloat16* gwl,
    const __nv_bfloat16* xh, const __nv_bfloat16* xl,
    int m0, int s0)
{
    int w = tid >> 5, lane = tid & 31;
    int rsel = lane & 15, csel = lane >> 4;

    conv_issue(smb, tid, 0, gwh, gwl, xh, xl, m0, s0);
    cpa_commit();

    for (int kc = 0; kc < 16; kc++) {
        cpa_wait_all();
        __syncthreads();
        if (kc < 15) {
            conv_issue(smb + ((kc + 1) & 1) * STG, tid, kc + 1, gwh, gwl, xh, xl, m0, s0);
            cpa_commit();
        }
        uint32_t base = smb + (kc & 1) * STG;
        uint32_t aW  = base + (16 * w + rsel) * 48 + csel * 16;
        uint32_t aWl = aW + WL_OFF;
        uint32_t aX  = base + XH_OFF + rsel * 272 + csel * 16;
        uint32_t aXl = aX + (XL_OFF - XH_OFF);

        uint32_t awh[4], awl[4];
        ldsm4(awh, aW);
        ldsm4(awl, aWl);
#pragma unroll
        for (int nt = 0; nt < 8; nt++) {
            uint32_t bxh[4], bxl[4];
            ldsm4t(bxh, aX + nt * 32);
            ldsm4t(bxl, aXl + nt * 32);
            float* oA = acc[2 * nt];
            float* oB = acc[2 * nt + 1];
            mma16816(oA, awh, bxh[0], bxh[1]);
            mma16816(oB, awh, bxh[2], bxh[3]);
            mma16816(oA, awh, bxl[0], bxl[1]);
            mma16816(oB, awh, bxl[2], bxl[3]);
            mma16816(oA, awl, bxh[0], bxh[1]);
            mma16816(oB, awl, bxh[2], bxh[3]);
        }
    }
}

__global__ __launch_bounds__(256) void qkv_mma_kernel(
    const float* __restrict__ bq, const float* __restrict__ bk, const float* __restrict__ bv)
{
    __shared__ __align__(16) char smem[2 * STG];
    int z = blockIdx.z, b = z / 3, which = z % 3;
    const __nv_bfloat16* gwh = g_wh + (size_t)which * 65536;
    const __nv_bfloat16* gwl = g_wl + (size_t)which * 65536;
    const float* bias = (which == 0) ? bq : (which == 1) ? bk : bv;
    void* ohv = (which == 0) ? (void*)g_qh : (which == 1) ? (void*)g_kh : (void*)g_vh;
    void* olv = (which == 0) ? (void*)g_ql : (which == 1) ? (void*)g_kl : (void*)g_vl;
    uint16_t* oh = (uint16_t*)ohv;
    uint16_t* ol = (uint16_t*)olv;
    int m0 = blockIdx.y * 128, s0 = blockIdx.x * 128;
    int tid = threadIdx.x;
    size_t ob = (size_t)b * CH * SP;
    const __nv_bfloat16* xh = g_xh + ob;
    const __nv_bfloat16* xl = g_xl + ob;

    float acc[16][4];
#pragma unroll
    for (int i = 0; i < 16; i++)
#pragma unroll
        for (int j = 0; j < 4; j++) acc[i][j] = 0.0f;

    conv_gemm_body(acc, sm_u32(smem), tid, gwh, gwl, xh, xl, m0, s0);

    int w = tid >> 5, lane = tid & 31;
    int r0 = 16 * w + (lane >> 2), c2 = (lane & 3) * 2;
    float b0 = bias[m0 + r0], b1 = bias[m0 + r0 + 8];
    size_t ro0 = ob + (size_t)(m0 + r0) * SP;
    size_t ro1 = ob + (size_t)(m0 + r0 + 8) * SP;
    bool f16out = (which == 2);
#pragma unroll
    for (int nt = 0; nt < 8; nt++) {
        int c = s0 + nt * 16 + c2;
        uint32_t hh, ll;
        float v0 = acc[2 * nt][0] + b0, v1 = acc[2 * nt][1] + b0;
        if (f16out) split2h(v0, v1, hh, ll); else split2(v0, v1, hh, ll);
        *(uint32_t*)&oh[ro0 + c] = hh;  *(uint32_t*)&ol[ro0 + c] = ll;
        v0 = acc[2 * nt][2] + b1; v1 = acc[2 * nt][3] + b1;
        if (f16out) split2h(v0, v1, hh, ll); else split2(v0, v1, hh, ll);
        *(uint32_t*)&oh[ro1 + c] = hh;  *(uint32_t*)&ol[ro1 + c] = ll;
        v0 = acc[2 * nt + 1][0] + b0; v1 = acc[2 * nt + 1][1] + b0;
        if (f16out) split2h(v0, v1, hh, ll); else split2(v0, v1, hh, ll);
        *(uint32_t*)&oh[ro0 + c + 8] = hh;  *(uint32_t*)&ol[ro0 + c + 8] = ll;
        v0 = acc[2 * nt + 1][2] + b1; v1 = acc[2 * nt + 1][3] + b1;
        if (f16out) split2h(v0, v1, hh, ll); else split2(v0, v1, hh, ll);
        *(uint32_t*)&oh[ro1 + c + 8] = hh;  *(uint32_t*)&ol[ro1 + c + 8] = ll;
    }
}

__global__ __launch_bounds__(256) void out_mma_kernel(
    const float* __restrict__ x, const float* __restrict__ bu, float* __restrict__ out)
{
    __shared__ __align__(16) char smem[2 * STG];
    int b = blockIdx.z;
    const __nv_bfloat16* gwh = g_wh + (size_t)3 * 65536;
    const __nv_bfloat16* gwl = g_wl + (size_t)3 * 65536;
    int m0 = blockIdx.y * 128, s0 = blockIdx.x * 128;
    int tid = threadIdx.x;
    size_t ob = (size_t)b * CH * SP;
    const __nv_bfloat16* ah = g_ah + ob;
    const __nv_bfloat16* al = g_al + ob;

    float acc[16][4];
#pragma unroll
    for (int i = 0; i < 16; i++)
#pragma unroll
        for (int j = 0; j < 4; j++) acc[i][j] = 0.0f;

    conv_gemm_body(acc, sm_u32(smem), tid, gwh, gwl, ah, al, m0, s0);

    int w = tid >> 5, lane = tid & 31;
    int r0 = 16 * w + (lane >> 2), c2 = (lane & 3) * 2;
    float b0 = bu[m0 + r0], b1 = bu[m0 + r0 + 8];
    size_t ro0 = ob + (size_t)(m0 + r0) * SP;
    size_t ro1 = ob + (size_t)(m0 + r0 + 8) * SP;
#pragma unroll
    for (int nt = 0; nt < 8; nt++) {
        int c = s0 + nt * 16 + c2;
        float2 x00 = *(const float2*)&x[ro0 + c];
        float2 x10 = *(const float2*)&x[ro1 + c];
        float2 x01 = *(const float2*)&x[ro0 + c + 8];
        float2 x11 = *(const float2*)&x[ro1 + c + 8];
        float2 v;
        v.x = acc[2 * nt][0] + b0 + x00.x;  v.y = acc[2 * nt][1] + b0 + x00.y;
        *(float2*)&out[ro0 + c] = v;
        v.x = acc[2 * nt][2] + b1 + x10.x;  v.y = acc[2 * nt][3] + b1 + x10.y;
        *(float2*)&out[ro1 + c] = v;
        v.x = acc[2 * nt + 1][0] + b0 + x01.x;  v.y = acc[2 * nt + 1][1] + b0 + x01.y;
        *(float2*)&out[ro0 + c + 8] = v;
        v.x = acc[2 * nt + 1][2] + b1 + x11.x;  v.y = acc[2 * nt + 1][3] + b1 + x11.y;
        *(float2*)&out[ro1 + c + 8] = v;
    }
}

// ---------------------------------------------------------------------------
// Flash attention. S: bf16 3-term (chain-broken). PV: fp16 1-term (Vh only).
// Quantized max (+4) with warp-vote rescale skip.
// grid (32 row-tiles of 128, 4 batches), 256 threads = 8 warps.
// ---------------------------------------------------------------------------
#define SQ 264
#define ATTN_SMEM ((2 * 128 * SQ + 3 * 32 * SQ) * 2)

__global__ __launch_bounds__(256, 1) void attn_kernel()
{
    extern __shared__ __nv_bfloat16 sm[];
    __nv_bfloat16* Qh = sm;
    __nv_bfloat16* Ql = Qh + 128 * SQ;
    __nv_bfloat16* Kh = Ql + 128 * SQ;
    __nv_bfloat16* Kl = Kh + 32 * SQ;
    __nv_bfloat16* Vh = Kl + 32 * SQ;   // fp16 bits

    int b = blockIdx.y;
    int n0 = blockIdx.x * 128;
    int tid = threadIdx.x;
    int w = tid >> 5, lane = tid & 31;

    size_t base = (size_t)b * CH * SP;
    const uint4* Qgh = (const uint4*)(g_qh + base);
    const uint4* Qgl = (const uint4*)(g_ql + base);
    const uint4* Kgh = (const uint4*)(g_kh + base);
    const uint4* Kgl = (const uint4*)(g_kl + base);
    const uint4* Vgh = (const uint4*)(g_vh + base);

    int lr0 = tid >> 3, lc0 = (tid & 7) * 4;
    uint32_t sKh = sm_u32(Kh), sKl = sm_u32(Kl), sVh = sm_u32(Vh);

    {
        size_t g = (size_t)lr0 * 32 + lc0;
        uint32_t s = (uint32_t)(lr0 * 33 + lc0) * 16;
#pragma unroll
        for (int j = 0; j < 4; j++) {
            cpa16(sKh + s + j * 16, Kgh + g + j);
            cpa16(sKl + s + j * 16, Kgl + g + j);
        }
        cpa_commit();
    }

    for (int idx = tid; idx < 128 * 32; idx += 256) {
        int r = idx >> 5, c = idx & 31;
        ((uint4*)Qh)[r * 33 + c] = Qgh[(size_t)(n0 + r) * 32 + c];
        ((uint4*)Ql)[r * 33 + c] = Qgl[(size_t)(n0 + r) * 32 + c];
    }

    int rsel = lane & 15, csel = lane >> 4;
    uint32_t aQh = sm_u32(Qh + (w * 16 + rsel) * SQ + csel * 8);
    uint32_t aQl = aQh + 128 * SQ * 2;
    uint32_t aKh = sm_u32(Kh + rsel * SQ + csel * 8);
    uint32_t aKl = aKh + 32 * SQ * 2;
    uint32_t aVh = sm_u32(Vh + rsel * SQ + csel * 8);

    float o[32][4];
#pragma unroll
    for (int i = 0; i < 32; i++)
#pragma unroll
        for (int j = 0; j < 4; j++) o[i][j] = 0.0f;
    float m0r = -1e30f, m1r = -1e30f, l0r = 0.0f, l1r = 0.0f;

    for (int mt = 0; mt < 128; mt++) {
        cpa_wait_all();
        __syncthreads();

        {
            size_t g = (size_t)(mt * 32 + lr0) * 32 + lc0;
            uint32_t s = (uint32_t)(lr0 * 33 + lc0) * 16;
#pragma unroll
            for (int j = 0; j < 4; j++)
                cpa16(sVh + s + j * 16, Vgh + g + j);
            cpa_commit();
        }

        // ---- S = Q K^T, bf16 3-term, split accumulators ----
        float sh[4][4], sl[4][4];
#pragma unroll
        for (int i = 0; i < 4; i++)
#pragma unroll
            for (int j = 0; j < 4; j++) { sh[i][j] = 0.0f; sl[i][j] = 0.0f; }

#pragma unroll
        for (int kc = 0; kc < 16; kc++) {
            uint32_t ah[4], al[4];
            ldsm4(ah, aQh + kc * 32);
            ldsm4(al, aQl + kc * 32);
#pragma unroll
            for (int np = 0; np < 2; np++) {
                uint32_t bh[4], bl[4];
                ldsm4(bh, aKh + np * (16 * SQ * 2) + kc * 32);
                ldsm4(bl, aKl + np * (16 * SQ * 2) + kc * 32);
                mma16816(sh[2 * np],     ah, bh[0], bh[2]);
                mma16816(sl[2 * np],     ah, bl[0], bl[2]);
                mma16816(sh[2 * np + 1], ah, bh[1], bh[3]);
                mma16816(sl[2 * np + 1], ah, bl[1], bl[3]);
                mma16816(sl[2 * np],     al, bh[0], bh[2]);
                mma16816(sl[2 * np + 1], al, bh[1], bh[3]);
            }
        }

        cpa_wait_all();
        __syncthreads();

        if (mt + 1 < 128) {
            size_t g = (size_t)((mt + 1) * 32 + lr0) * 32 + lc0;
            uint32_t s2 = (uint32_t)(lr0 * 33 + lc0) * 16;
#pragma unroll
            for (int j = 0; j < 4; j++) {
                cpa16(sKh + s2 + j * 16, Kgh + g + j);
                cpa16(sKl + s2 + j * 16, Kgl + g + j);
            }
            cpa_commit();
        }

        float s[4][4];
#pragma unroll
        for (int i = 0; i < 4; i++)
#pragma unroll
            for (int j = 0; j < 4; j++) s[i][j] = sh[i][j] + sl[i][j];

        float mx0 = s[0][0], mx1 = s[0][2];
#pragma unroll
        for (int nt = 0; nt < 4; nt++) {
            mx0 = fmaxf(mx0, fmaxf(s[nt][0], s[nt][1]));
            mx1 = fmaxf(mx1, fmaxf(s[nt][2], s[nt][3]));
        }
        mx0 = fmaxf(mx0, __shfl_xor_sync(0xffffffffu, mx0, 1));
        mx0 = fmaxf(mx0, __shfl_xor_sync(0xffffffffu, mx0, 2));
        mx1 = fmaxf(mx1, __shfl_xor_sync(0xffffffffu, mx1, 1));
        mx1 = fmaxf(mx1, __shfl_xor_sync(0xffffffffu, mx1, 2));

        // quantized max: pad +4 on rise so most iterations skip the rescale
        bool ch0 = mx0 > m0r, ch1 = mx1 > m1r;
        float mn0 = ch0 ? mx0 + 4.0f : m0r;
        float mn1 = ch1 ? mx1 + 4.0f : m1r;
        float sc0 = ch0 ? __expf(m0r - mn0) : 1.0f;
        float sc1 = ch1 ? __expf(m1r - mn1) : 1.0f;
        m0r = mn0; m1r = mn1;

        float rs0 = 0.0f, rs1 = 0.0f;
#pragma unroll
        for (int nt = 0; nt < 4; nt++) {
            s[nt][0] = __expf(s[nt][0] - mn0);
            s[nt][1] = __expf(s[nt][1] - mn0);
            s[nt][2] = __expf(s[nt][2] - mn1);
            s[nt][3] = __expf(s[nt][3] - mn1);
            rs0 += s[nt][0] + s[nt][1];
            rs1 += s[nt][2] + s[nt][3];
        }
        rs0 += __shfl_xor_sync(0xffffffffu, rs0, 1);
        rs0 += __shfl_xor_sync(0xffffffffu, rs0, 2);
        rs1 += __shfl_xor_sync(0xffffffffu, rs1, 1);
        rs1 += __shfl_xor_sync(0xffffffffu, rs1, 2);
        l0r = l0r * sc0 + rs0;
        l1r = l1r * sc1 + rs1;

        // O rescale only when some lane's max rose (warp-vote; sc=1 lanes harmless)
        if (__any_sync(0xffffffffu, ch0 || ch1)) {
#pragma unroll
            for (int nt = 0; nt < 32; nt++) {
                o[nt][0] *= sc0; o[nt][1] *= sc0;
                o[nt][2] *= sc1; o[nt][3] *= sc1;
            }
        }

        // P -> fp16 A-fragments
        uint32_t ph[2][4];
#pragma unroll
        for (int kc = 0; kc < 2; kc++) {
            int nt0 = 2 * kc, nt1 = 2 * kc + 1;
            ph[kc][0] = pkh(s[nt0][0], s[nt0][1]);
            ph[kc][1] = pkh(s[nt0][2], s[nt0][3]);
            ph[kc][2] = pkh(s[nt1][0], s[nt1][1]);
            ph[kc][3] = pkh(s[nt1][2], s[nt1][3]);
        }

        // ---- O += Ph Vh (fp16, 1-term) ----
#pragma unroll
        for (int kc = 0; kc < 2; kc++) {
#pragma unroll
            for (int ct = 0; ct < 16; ct++) {
                uint32_t vh[4];
                ldsm4t(vh, aVh + kc * (16 * SQ * 2) + ct * 32);
                mma16816h(o[2 * ct],     ph[kc], vh[0], vh[1]);
                mma16816h(o[2 * ct + 1], ph[kc], vh[2], vh[3]);
            }
        }
    }

    // epilogue: normalize, store bf16 hi/lo
    float inv0 = 1.0f / l0r, inv1 = 1.0f / l1r;
    int r0 = n0 + w * 16 + (lane >> 2);
    int r1 = r0 + 8;
    int cb = (lane & 3) * 2;
#pragma unroll
    for (int nt = 0; nt < 32; nt++) {
        int c = nt * 8 + cb;
        uint32_t hh, ll;
        split2(o[nt][0] * inv0, o[nt][1] * inv0, hh, ll);
        *(uint32_t*)&g_ah[base + (size_t)r0 * 256 + c] = hh;
        *(uint32_t*)&g_al[base + (size_t)r0 * 256 + c] = ll;
        split2(o[nt][2] * inv1, o[nt][3] * inv1, hh, ll);
        *(uint32_t*)&g_ah[base + (size_t)r1 * 256 + c] = hh;
        *(uint32_t*)&g_al[base + (size_t)r1 * 256 + c] = ll;
    }
}

// ---------------------------------------------------------------------------
extern "C" void kernel_launch(void* const* d_in, const int* in_sizes, int n_in,
                              void* d_out, int out_size)
{
    (void)in_sizes; (void)n_in; (void)out_size;
    const float* x  = (const float*)d_in[0];
    const float* Wq = (const float*)d_in[1];
    const float* bq = (const float*)d_in[2];
    const float* Wk = (const float*)d_in[3];
    const float* bk = (const float*)d_in[4];
    const float* Wv = (const float*)d_in[5];
    const float* bv = (const float*)d_in[6];
    const float* Wu = (const float*)d_in[7];
    const float* bu = (const float*)d_in[8];
    float* out = (float*)d_out;

    cudaFuncSetAttribute(attn_kernel, cudaFuncAttributeMaxDynamicSharedMemorySize, ATTN_SMEM);

    splitx_kernel<<<4096, 256>>>(x);
    splitw_kernel<<<256, 256>>>(Wq, Wk, Wv, Wu);
    qkv_mma_kernel<<<dim3(32, 2, 12), 256>>>(bq, bk, bv);
    attn_kernel<<<dim3(32, 4), 256, ATTN_SMEM>>>();
    out_mma_kernel<<<dim3(32, 2, 4), 256>>>(x, bu, out);
}